// round 2
// baseline (speedup 1.0000x reference)
#include <cuda_runtime.h>
#include <cmath>

#define BATCH 2
#define SEQ   2048
#define CH    1024
#define NH    16
#define SST   16
#define HDIM  64
#define NTOK  (BATCH*SEQ)   // 4096

// ---------------- device scratch (allocation-free) --------------------------
__device__ float g_xb[(size_t)NTOK*CH];
__device__ float g_dl[(size_t)NTOK*CH];
__device__ float g_Bm[(size_t)NTOK*SST];
__device__ float g_Cm[(size_t)NTOK*SST];
__device__ float g_y [(size_t)NTOK*CH];
__device__ float g_hy[(size_t)NTOK*CH];
__device__ float g_Q [(size_t)NTOK*CH];   // (B,H,T,HD)
__device__ float g_K [(size_t)NTOK*CH];
__device__ float g_V [(size_t)NTOK*CH];
__device__ float g_at[(size_t)NTOK*CH];   // attention out, (B,T,C)

__device__ __forceinline__ float softplus_f(float x) {
    return (x > 20.f) ? x : log1pf(expf(x));
}

// ---------------- SGEMM: 128x128 tile, K-tile 8, 256 thr, 8x8 microtile -----
// A: MxK row-major.  W: KxN row-major.  out = A@W + bias (epilogue variants).
// flags bit0: softplus epilogue.  flags bit1: write in (B,H,T,HD) head layout.
__global__ __launch_bounds__(256, 2)
void sgemm_k(const float* __restrict__ A, const float* __restrict__ W,
             const float* __restrict__ bias, float* __restrict__ out,
             int M, int N, int K, int flags)
{
    __shared__ float As[8][128];
    __shared__ float Bs[8][128];
    const int tid = threadIdx.x;
    const int tx = tid & 15, ty = tid >> 4;
    const int row0 = blockIdx.y << 7;
    const int col0 = blockIdx.x << 7;

    float acc[8][8];
    #pragma unroll
    for (int i = 0; i < 8; i++)
        #pragma unroll
        for (int j = 0; j < 8; j++) acc[i][j] = 0.f;

    const int arow = tid >> 1, acol = (tid & 1) << 2;
    const int brow = tid >> 5, bcol = (tid & 31) << 2;
    const float* Aptr = A + (size_t)(row0 + arow) * K + acol;
    const float* Wptr = W + (size_t)brow * N + col0 + bcol;

    for (int k0 = 0; k0 < K; k0 += 8) {
        float4 av = *(const float4*)(Aptr + k0);
        float4 wv = *(const float4*)(Wptr + (size_t)k0 * N);
        __syncthreads();
        As[acol + 0][arow] = av.x;
        As[acol + 1][arow] = av.y;
        As[acol + 2][arow] = av.z;
        As[acol + 3][arow] = av.w;
        *(float4*)&Bs[brow][bcol] = wv;
        __syncthreads();
        #pragma unroll
        for (int kk = 0; kk < 8; kk++) {
            float a[8], b[8];
            *(float4*)&a[0] = *(const float4*)&As[kk][ty * 4];
            *(float4*)&a[4] = *(const float4*)&As[kk][64 + ty * 4];
            *(float4*)&b[0] = *(const float4*)&Bs[kk][tx * 4];
            *(float4*)&b[4] = *(const float4*)&Bs[kk][64 + tx * 4];
            #pragma unroll
            for (int i = 0; i < 8; i++)
                #pragma unroll
                for (int j = 0; j < 8; j++)
                    acc[i][j] = fmaf(a[i], b[j], acc[i][j]);
        }
    }

    float bs[8];
    *(float4*)&bs[0] = *(const float4*)&bias[col0 + tx * 4];
    *(float4*)&bs[4] = *(const float4*)&bias[col0 + 64 + tx * 4];

    #pragma unroll
    for (int i = 0; i < 8; i++) {
        int row = row0 + ((i < 4) ? (ty * 4 + i) : (64 + ty * 4 + i - 4));
        #pragma unroll
        for (int jg = 0; jg < 2; jg++) {
            int col = col0 + jg * 64 + tx * 4;
            float4 v;
            v.x = acc[i][jg * 4 + 0] + bs[jg * 4 + 0];
            v.y = acc[i][jg * 4 + 1] + bs[jg * 4 + 1];
            v.z = acc[i][jg * 4 + 2] + bs[jg * 4 + 2];
            v.w = acc[i][jg * 4 + 3] + bs[jg * 4 + 3];
            if (flags & 1) {
                v.x = softplus_f(v.x); v.y = softplus_f(v.y);
                v.z = softplus_f(v.z); v.w = softplus_f(v.w);
            }
            size_t dst;
            if (flags & 2) {
                int bb = row >> 11;        // token / SEQ
                int t  = row & (SEQ - 1);
                int hh = col >> 6;         // head
                int hd = col & (HDIM - 1);
                dst = ((((size_t)bb * NH + hh) * SEQ) + t) * HDIM + hd;
            } else {
                dst = (size_t)row * N + col;
            }
            *(float4*)&out[dst] = v;
        }
    }
}

// ---------------- small B/C projection: out = x @ WB | x @ WC (N=16 each) ---
__global__ __launch_bounds__(256)
void bc_k(const float* __restrict__ x, const float* __restrict__ WB,
          const float* __restrict__ WC, float* __restrict__ Bm,
          float* __restrict__ Cm)
{
    __shared__ float xs[8][64];
    __shared__ float Ws[64][32];
    const int tid = threadIdx.x;
    const int tx = tid & 31, ty = tid >> 5;   // ty: token within block (8)
    const int tok0 = blockIdx.x * 8;
    float acc = 0.f;

    for (int k0 = 0; k0 < CH; k0 += 64) {
        __syncthreads();
        if (tid < 128) {
            int t = tid >> 4, c4 = (tid & 15) * 4;
            *(float4*)&xs[t][c4] =
                *(const float4*)&x[(size_t)(tok0 + t) * CH + k0 + c4];
        }
        {
            int r = tid >> 2, c = (tid & 3) * 4;
            *(float4*)&Ws[r][c]      = *(const float4*)&WB[(size_t)(k0 + r) * SST + c];
            *(float4*)&Ws[r][16 + c] = *(const float4*)&WC[(size_t)(k0 + r) * SST + c];
        }
        __syncthreads();
        #pragma unroll
        for (int k = 0; k < 64; k++)
            acc = fmaf(xs[ty][k], Ws[k][tx], acc);
    }
    int tok = tok0 + ty;
    if (tx < 16) Bm[(size_t)tok * SST + tx] = acc;
    else         Cm[(size_t)tok * SST + (tx - 16)] = acc;
}

// ---------------- Mamba-style scan ------------------------------------------
// grid (CH/64, BATCH), 64 threads. Each thread owns one channel, carries h[16].
#define SC_CH 64
#define SC_TC 8
__global__ __launch_bounds__(64)
void scan_k(const float* __restrict__ xb, const float* __restrict__ dl,
            const float* __restrict__ Bm, const float* __restrict__ Cm,
            const float* __restrict__ A_log, float* __restrict__ y)
{
    __shared__ float sd[2][SC_TC][SC_CH];
    __shared__ float sx[2][SC_TC][SC_CH];
    __shared__ float sB[2][SC_TC * SST];
    __shared__ float sC[2][SC_TC * SST];

    const int tid = threadIdx.x;
    const int b = blockIdx.y;
    const int cbase = blockIdx.x * SC_CH;
    const int c = cbase + tid;

    float A[SST];
    #pragma unroll
    for (int s = 0; s < SST; s++) A[s] = -expf(A_log[(size_t)c * SST + s]);
    float h[SST];
    #pragma unroll
    for (int s = 0; s < SST; s++) h[s] = 0.f;

    float rd[SC_TC], rx[SC_TC], rB[2], rC[2];
    const int nch = SEQ / SC_TC;

    // chunk 0
    {
        size_t base = ((size_t)(b * SEQ)) * CH + cbase + tid;
        #pragma unroll
        for (int i = 0; i < SC_TC; i++) {
            rd[i] = dl[base + (size_t)i * CH];
            rx[i] = xb[base + (size_t)i * CH];
        }
        size_t bc = ((size_t)(b * SEQ)) * SST;
        rB[0] = Bm[bc + tid];      rB[1] = Bm[bc + 64 + tid];
        rC[0] = Cm[bc + tid];      rC[1] = Cm[bc + 64 + tid];
    }
    #pragma unroll
    for (int i = 0; i < SC_TC; i++) { sd[0][i][tid] = rd[i]; sx[0][i][tid] = rx[i]; }
    sB[0][tid] = rB[0]; sB[0][64 + tid] = rB[1];
    sC[0][tid] = rC[0]; sC[0][64 + tid] = rC[1];
    __syncthreads();

    for (int ck = 0; ck < nch; ck++) {
        const int p = ck & 1;
        if (ck + 1 < nch) {
            int t0 = (ck + 1) * SC_TC;
            size_t base = ((size_t)(b * SEQ + t0)) * CH + cbase + tid;
            #pragma unroll
            for (int i = 0; i < SC_TC; i++) {
                rd[i] = dl[base + (size_t)i * CH];
                rx[i] = xb[base + (size_t)i * CH];
            }
            size_t bc = ((size_t)(b * SEQ + t0)) * SST;
            rB[0] = Bm[bc + tid];  rB[1] = Bm[bc + 64 + tid];
            rC[0] = Cm[bc + tid];  rC[1] = Cm[bc + 64 + tid];
        }
        #pragma unroll
        for (int i = 0; i < SC_TC; i++) {
            float d  = sd[p][i][tid];
            float xv = sx[p][i][tid];
            float dx = d * xv;
            float yv = 0.f;
            #pragma unroll
            for (int s = 0; s < SST; s++) {
                float bar = __expf(d * A[s]);
                float hh = fmaf(bar, h[s], dx * sB[p][i * SST + s]);
                h[s] = hh;
                yv = fmaf(hh, sC[p][i * SST + s], yv);
            }
            y[((size_t)(b * SEQ + ck * SC_TC + i)) * CH + c] = yv;
        }
        if (ck + 1 < nch) {
            const int q = (ck + 1) & 1;
            #pragma unroll
            for (int i = 0; i < SC_TC; i++) { sd[q][i][tid] = rd[i]; sx[q][i][tid] = rx[i]; }
            sB[q][tid] = rB[0]; sB[q][64 + tid] = rB[1];
            sC[q][tid] = rC[0]; sC[q][64 + tid] = rC[1];
        }
        __syncthreads();
    }
}

// ---------------- LayerNorm(x_base + y) -------------------------------------
__global__ __launch_bounds__(256)
void ln_k(const float* __restrict__ xb, const float* __restrict__ y,
          const float* __restrict__ gam, const float* __restrict__ bet,
          float* __restrict__ out)
{
    const int tok = blockIdx.x, tid = threadIdx.x;
    const float4* a4 = (const float4*)(xb + (size_t)tok * CH);
    const float4* b4 = (const float4*)(y  + (size_t)tok * CH);
    float4 v = a4[tid], w = b4[tid];
    v.x += w.x; v.y += w.y; v.z += w.z; v.w += w.w;
    float sum = v.x + v.y + v.z + v.w;
    float sq  = v.x * v.x + v.y * v.y + v.z * v.z + v.w * v.w;
    #pragma unroll
    for (int off = 16; off; off >>= 1) {
        sum += __shfl_xor_sync(0xffffffffu, sum, off);
        sq  += __shfl_xor_sync(0xffffffffu, sq,  off);
    }
    __shared__ float s1[8], s2[8];
    __shared__ float mu_s, rstd_s;
    if ((tid & 31) == 0) { s1[tid >> 5] = sum; s2[tid >> 5] = sq; }
    __syncthreads();
    if (tid == 0) {
        float t1 = 0.f, t2 = 0.f;
        #pragma unroll
        for (int i = 0; i < 8; i++) { t1 += s1[i]; t2 += s2[i]; }
        float mu = t1 * (1.f / CH);
        float var = t2 * (1.f / CH) - mu * mu;
        mu_s = mu;
        rstd_s = rsqrtf(var + 1e-5f);
    }
    __syncthreads();
    float mu = mu_s, rstd = rstd_s;
    float4 g = ((const float4*)gam)[tid];
    float4 be = ((const float4*)bet)[tid];
    float4 o;
    o.x = (v.x - mu) * rstd * g.x + be.x;
    o.y = (v.y - mu) * rstd * g.y + be.y;
    o.z = (v.z - mu) * rstd * g.z + be.z;
    o.w = (v.w - mu) * rstd * g.w + be.w;
    ((float4*)(out + (size_t)tok * CH))[tid] = o;
}

// ---------------- causal flash attention (fp32) ------------------------------
// grid (T/64, B*H), 256 threads. 64q x 64k tiles, P aliased into K buffer.
__global__ __launch_bounds__(256)
void flash_k(const float* __restrict__ Q, const float* __restrict__ K,
             const float* __restrict__ V, const float* __restrict__ temp,
             float* __restrict__ out)
{
    __shared__ float sQ[64 * 64];
    __shared__ float sKP[64 * 64];   // K^T, later aliased with P
    __shared__ float sV[64 * 64];

    const int tid = threadIdx.x;
    const int tx = tid & 15, ty = tid >> 4;
    const int qt = blockIdx.x, bh = blockIdx.y;
    const int b = bh >> 4, h = bh & 15;
    const int q0 = qt << 6;
    const float* Qg = Q + (size_t)bh * SEQ * HDIM;
    const float* Kg = K + (size_t)bh * SEQ * HDIM;
    const float* Vg = V + (size_t)bh * SEQ * HDIM;

    const float tv = temp[h];
    const float qk_scale = softplus_f(tv) * 0.125f;  // 1/sqrt(64)

    // load Q tile transposed: sQ[d][i]
    {
        const int r = tid >> 4;
        const int d4 = (tid & 15) << 2;
        #pragma unroll
        for (int rep = 0; rep < 4; rep++) {
            int rr = rep * 16 + r;
            float4 v = *(const float4*)&Qg[(size_t)(q0 + rr) * HDIM + d4];
            sQ[(d4 + 0) * 64 + rr] = v.x;
            sQ[(d4 + 1) * 64 + rr] = v.y;
            sQ[(d4 + 2) * 64 + rr] = v.z;
            sQ[(d4 + 3) * 64 + rr] = v.w;
        }
    }

    float o[4][4];
    #pragma unroll
    for (int a = 0; a < 4; a++)
        #pragma unroll
        for (int c = 0; c < 4; c++) o[a][c] = 0.f;
    float m[4] = {-1e30f, -1e30f, -1e30f, -1e30f};
    float l[4] = {0.f, 0.f, 0.f, 0.f};

    for (int kt = 0; kt <= qt; kt++) {
        const int k0 = kt << 6;
        __syncthreads();  // previous PV reads done; first iter: Q stores visible
        {
            const int r = tid >> 4;
            const int d4 = (tid & 15) << 2;
            #pragma unroll
            for (int rep = 0; rep < 4; rep++) {
                int rr = rep * 16 + r;
                float4 kv = *(const float4*)&Kg[(size_t)(k0 + rr) * HDIM + d4];
                sKP[(d4 + 0) * 64 + rr] = kv.x;
                sKP[(d4 + 1) * 64 + rr] = kv.y;
                sKP[(d4 + 2) * 64 + rr] = kv.z;
                sKP[(d4 + 3) * 64 + rr] = kv.w;
                float4 vv = *(const float4*)&Vg[(size_t)(k0 + rr) * HDIM + d4];
                *(float4*)&sV[rr * 64 + d4] = vv;
            }
        }
        __syncthreads();

        // S = Q K^T  (4x4 microtile per thread)
        float s[4][4];
        #pragma unroll
        for (int a = 0; a < 4; a++)
            #pragma unroll
            for (int c = 0; c < 4; c++) s[a][c] = 0.f;
        #pragma unroll 16
        for (int d = 0; d < 64; d++) {
            float4 qa = *(const float4*)&sQ[d * 64 + ty * 4];
            float4 kb = *(const float4*)&sKP[d * 64 + tx * 4];
            s[0][0] = fmaf(qa.x, kb.x, s[0][0]); s[0][1] = fmaf(qa.x, kb.y, s[0][1]);
            s[0][2] = fmaf(qa.x, kb.z, s[0][2]); s[0][3] = fmaf(qa.x, kb.w, s[0][3]);
            s[1][0] = fmaf(qa.y, kb.x, s[1][0]); s[1][1] = fmaf(qa.y, kb.y, s[1][1]);
            s[1][2] = fmaf(qa.y, kb.z, s[1][2]); s[1][3] = fmaf(qa.y, kb.w, s[1][3]);
            s[2][0] = fmaf(qa.z, kb.x, s[2][0]); s[2][1] = fmaf(qa.z, kb.y, s[2][1]);
            s[2][2] = fmaf(qa.z, kb.z, s[2][2]); s[2][3] = fmaf(qa.z, kb.w, s[2][3]);
            s[3][0] = fmaf(qa.w, kb.x, s[3][0]); s[3][1] = fmaf(qa.w, kb.y, s[3][1]);
            s[3][2] = fmaf(qa.w, kb.z, s[3][2]); s[3][3] = fmaf(qa.w, kb.w, s[3][3]);
        }
        #pragma unroll
        for (int a = 0; a < 4; a++)
            #pragma unroll
            for (int c = 0; c < 4; c++) s[a][c] *= qk_scale;
        if (kt == qt) {   // causal mask only on diagonal tile
            #pragma unroll
            for (int a = 0; a < 4; a++)
                #pragma unroll
                for (int c = 0; c < 4; c++)
                    if (k0 + tx * 4 + c > q0 + ty * 4 + a) s[a][c] = -1e30f;
        }

        // online softmax (row groups of 16 lanes share ty)
        float fac[4];
        #pragma unroll
        for (int a = 0; a < 4; a++) {
            float rm = fmaxf(fmaxf(s[a][0], s[a][1]), fmaxf(s[a][2], s[a][3]));
            #pragma unroll
            for (int off = 1; off < 16; off <<= 1)
                rm = fmaxf(rm, __shfl_xor_sync(0xffffffffu, rm, off));
            float mnew = fmaxf(m[a], rm);
            fac[a] = __expf(m[a] - mnew);
            m[a] = mnew;
            float rs = 0.f;
            #pragma unroll
            for (int c = 0; c < 4; c++) {
                float pv = __expf(s[a][c] - mnew);
                s[a][c] = pv;
                rs += pv;
            }
            #pragma unroll
            for (int off = 1; off < 16; off <<= 1)
                rs += __shfl_xor_sync(0xffffffffu, rs, off);
            l[a] = l[a] * fac[a] + rs;
        }
        #pragma unroll
        for (int a = 0; a < 4; a++)
            #pragma unroll
            for (int c = 0; c < 4; c++) o[a][c] *= fac[a];

        __syncthreads();  // all S reads of sKP done before P overwrite
        #pragma unroll
        for (int c = 0; c < 4; c++) {
            float4 pv = make_float4(s[0][c], s[1][c], s[2][c], s[3][c]);
            *(float4*)&sKP[(tx * 4 + c) * 64 + ty * 4] = pv;  // P[j][i]
        }
        __syncthreads();

        // O += P V
        #pragma unroll 16
        for (int jj = 0; jj < 64; jj++) {
            float4 pa = *(const float4*)&sKP[jj * 64 + ty * 4];
            float4 vb = *(const float4*)&sV[jj * 64 + tx * 4];
            o[0][0] = fmaf(pa.x, vb.x, o[0][0]); o[0][1] = fmaf(pa.x, vb.y, o[0][1]);
            o[0][2] = fmaf(pa.x, vb.z, o[0][2]); o[0][3] = fmaf(pa.x, vb.w, o[0][3]);
            o[1][0] = fmaf(pa.y, vb.x, o[1][0]); o[1][1] = fmaf(pa.y, vb.y, o[1][1]);
            o[1][2] = fmaf(pa.y, vb.z, o[1][2]); o[1][3] = fmaf(pa.y, vb.w, o[1][3]);
            o[2][0] = fmaf(pa.z, vb.x, o[2][0]); o[2][1] = fmaf(pa.z, vb.y, o[2][1]);
            o[2][2] = fmaf(pa.z, vb.z, o[2][2]); o[2][3] = fmaf(pa.z, vb.w, o[2][3]);
            o[3][0] = fmaf(pa.w, vb.x, o[3][0]); o[3][1] = fmaf(pa.w, vb.y, o[3][1]);
            o[3][2] = fmaf(pa.w, vb.z, o[3][2]); o[3][3] = fmaf(pa.w, vb.w, o[3][3]);
        }
    }

    // epilogue: out in (B,T,C) layout
    #pragma unroll
    for (int a = 0; a < 4; a++) {
        float inv = 1.f / l[a];
        int qrow = q0 + ty * 4 + a;
        float4 v = make_float4(o[a][0] * inv, o[a][1] * inv,
                               o[a][2] * inv, o[a][3] * inv);
        *(float4*)&out[((size_t)(b * SEQ + qrow)) * CH + h * HDIM + tx * 4] = v;
    }
}

// ---------------- launcher ---------------------------------------------------
extern "C" void kernel_launch(void* const* d_in, const int* in_sizes, int n_in,
                              void* d_out, int out_size)
{
    const float* x     = (const float*)d_in[0];
    const float* A_log = (const float*)d_in[1];
    const float* Wd    = (const float*)d_in[2];
    const float* bd    = (const float*)d_in[3];
    const float* WB    = (const float*)d_in[4];
    const float* WC    = (const float*)d_in[5];
    const float* Wq    = (const float*)d_in[6];
    const float* bq    = (const float*)d_in[7];
    const float* Wk    = (const float*)d_in[8];
    const float* bk    = (const float*)d_in[9];
    const float* Wv    = (const float*)d_in[10];
    const float* bv    = (const float*)d_in[11];
    const float* Wx    = (const float*)d_in[12];
    const float* bx    = (const float*)d_in[13];
    const float* Wo    = (const float*)d_in[14];
    const float* bo    = (const float*)d_in[15];
    const float* ln_g  = (const float*)d_in[16];
    const float* ln_b  = (const float*)d_in[17];
    const float* temp  = (const float*)d_in[18];
    float* out = (float*)d_out;

    float* xb = nullptr; cudaGetSymbolAddress((void**)&xb, g_xb);
    float* dl = nullptr; cudaGetSymbolAddress((void**)&dl, g_dl);
    float* Bm = nullptr; cudaGetSymbolAddress((void**)&Bm, g_Bm);
    float* Cm = nullptr; cudaGetSymbolAddress((void**)&Cm, g_Cm);
    float* yb = nullptr; cudaGetSymbolAddress((void**)&yb, g_y);
    float* hy = nullptr; cudaGetSymbolAddress((void**)&hy, g_hy);
    float* Qb = nullptr; cudaGetSymbolAddress((void**)&Qb, g_Q);
    float* Kb = nullptr; cudaGetSymbolAddress((void**)&Kb, g_K);
    float* Vb = nullptr; cudaGetSymbolAddress((void**)&Vb, g_V);
    float* at = nullptr; cudaGetSymbolAddress((void**)&at, g_at);

    dim3 gemm_grid(CH / 128, NTOK / 128);   // (8, 32)

    // x_base = x@Wx + bx ; delta = softplus(x@Wd + bd)
    sgemm_k<<<gemm_grid, 256>>>(x, Wx, bx, xb, NTOK, CH, CH, 0);
    sgemm_k<<<gemm_grid, 256>>>(x, Wd, bd, dl, NTOK, CH, CH, 1);
    // B_mat / C_mat
    bc_k<<<NTOK / 8, 256>>>(x, WB, WC, Bm, Cm);
    // recurrent scan -> y
    scan_k<<<dim3(CH / SC_CH, BATCH), SC_CH>>>(xb, dl, Bm, Cm, A_log, yb);
    // LayerNorm(x_base + y) -> hy
    ln_k<<<NTOK, 256>>>(xb, yb, ln_g, ln_b, hy);
    // Q,K,V (head layout)
    sgemm_k<<<gemm_grid, 256>>>(hy, Wq, bq, Qb, NTOK, CH, CH, 2);
    sgemm_k<<<gemm_grid, 256>>>(hy, Wk, bk, Kb, NTOK, CH, CH, 2);
    sgemm_k<<<gemm_grid, 256>>>(hy, Wv, bv, Vb, NTOK, CH, CH, 2);
    // attention
    flash_k<<<dim3(SEQ / 64, BATCH * NH), 256>>>(Qb, Kb, Vb, temp, at);
    // final projection
    sgemm_k<<<gemm_grid, 256>>>(at, Wo, bo, out, NTOK, CH, CH, 0);
}

// round 3
// speedup vs baseline: 1.1383x; 1.1383x over previous
#include <cuda_runtime.h>
#include <cmath>

#define BATCH 2
#define SEQ   2048
#define CH    1024
#define NH    16
#define SST   16
#define HDIM  64
#define NTOK  (BATCH*SEQ)   // 4096

#define NCH   32            // time chunks for parallel scan
#define CLEN  (SEQ/NCH)     // 64 steps per chunk
#define SGRP  16            // staging group (steps)

// ---------------- device scratch (allocation-free) --------------------------
__device__ float g_xb[(size_t)NTOK*CH];
__device__ float g_dl[(size_t)NTOK*CH];
__device__ float g_Bm[(size_t)NTOK*SST];
__device__ float g_Cm[(size_t)NTOK*SST];
__device__ float g_y [(size_t)NTOK*CH];
__device__ float g_hy[(size_t)NTOK*CH];
__device__ float g_Q [(size_t)NTOK*CH];   // (B,H,T,HD)
__device__ float g_K [(size_t)NTOK*CH];
__device__ float g_V [(size_t)NTOK*CH];
__device__ float g_at[(size_t)NTOK*CH];   // attention out, (B,T,C)
// parallel-scan intermediates
__device__ float g_hloc[(size_t)BATCH*NCH*CH*SST];  // per-chunk local end state
__device__ float g_hin [(size_t)BATCH*NCH*CH*SST];  // per-chunk incoming state
__device__ float g_dsum[(size_t)BATCH*NCH*CH];      // per-chunk sum of delta

__device__ __forceinline__ float softplus_f(float x) {
    return (x > 20.f) ? x : log1pf(expf(x));
}

// ---------------- SGEMM: 128x128 tile, K-tile 8, 256 thr, 8x8 microtile -----
// flags bit0: softplus epilogue.  flags bit1: write in (B,H,T,HD) head layout.
__global__ __launch_bounds__(256, 2)
void sgemm_k(const float* __restrict__ A, const float* __restrict__ W,
             const float* __restrict__ bias, float* __restrict__ out,
             int M, int N, int K, int flags)
{
    __shared__ float As[8][128];
    __shared__ float Bs[8][128];
    const int tid = threadIdx.x;
    const int tx = tid & 15, ty = tid >> 4;
    const int row0 = blockIdx.y << 7;
    const int col0 = blockIdx.x << 7;

    float acc[8][8];
    #pragma unroll
    for (int i = 0; i < 8; i++)
        #pragma unroll
        for (int j = 0; j < 8; j++) acc[i][j] = 0.f;

    const int arow = tid >> 1, acol = (tid & 1) << 2;
    const int brow = tid >> 5, bcol = (tid & 31) << 2;
    const float* Aptr = A + (size_t)(row0 + arow) * K + acol;
    const float* Wptr = W + (size_t)brow * N + col0 + bcol;

    for (int k0 = 0; k0 < K; k0 += 8) {
        float4 av = *(const float4*)(Aptr + k0);
        float4 wv = *(const float4*)(Wptr + (size_t)k0 * N);
        __syncthreads();
        As[acol + 0][arow] = av.x;
        As[acol + 1][arow] = av.y;
        As[acol + 2][arow] = av.z;
        As[acol + 3][arow] = av.w;
        *(float4*)&Bs[brow][bcol] = wv;
        __syncthreads();
        #pragma unroll
        for (int kk = 0; kk < 8; kk++) {
            float a[8], b[8];
            *(float4*)&a[0] = *(const float4*)&As[kk][ty * 4];
            *(float4*)&a[4] = *(const float4*)&As[kk][64 + ty * 4];
            *(float4*)&b[0] = *(const float4*)&Bs[kk][tx * 4];
            *(float4*)&b[4] = *(const float4*)&Bs[kk][64 + tx * 4];
            #pragma unroll
            for (int i = 0; i < 8; i++)
                #pragma unroll
                for (int j = 0; j < 8; j++)
                    acc[i][j] = fmaf(a[i], b[j], acc[i][j]);
        }
    }

    float bs[8];
    *(float4*)&bs[0] = *(const float4*)&bias[col0 + tx * 4];
    *(float4*)&bs[4] = *(const float4*)&bias[col0 + 64 + tx * 4];

    #pragma unroll
    for (int i = 0; i < 8; i++) {
        int row = row0 + ((i < 4) ? (ty * 4 + i) : (64 + ty * 4 + i - 4));
        #pragma unroll
        for (int jg = 0; jg < 2; jg++) {
            int col = col0 + jg * 64 + tx * 4;
            float4 v;
            v.x = acc[i][jg * 4 + 0] + bs[jg * 4 + 0];
            v.y = acc[i][jg * 4 + 1] + bs[jg * 4 + 1];
            v.z = acc[i][jg * 4 + 2] + bs[jg * 4 + 2];
            v.w = acc[i][jg * 4 + 3] + bs[jg * 4 + 3];
            if (flags & 1) {
                v.x = softplus_f(v.x); v.y = softplus_f(v.y);
                v.z = softplus_f(v.z); v.w = softplus_f(v.w);
            }
            size_t dst;
            if (flags & 2) {
                int bb = row >> 11;
                int t  = row & (SEQ - 1);
                int hh = col >> 6;
                int hd = col & (HDIM - 1);
                dst = ((((size_t)bb * NH + hh) * SEQ) + t) * HDIM + hd;
            } else {
                dst = (size_t)row * N + col;
            }
            *(float4*)&out[dst] = v;
        }
    }
}

// ---------------- small B/C projection ---------------------------------------
__global__ __launch_bounds__(256)
void bc_k(const float* __restrict__ x, const float* __restrict__ WB,
          const float* __restrict__ WC, float* __restrict__ Bm,
          float* __restrict__ Cm)
{
    __shared__ float xs[8][64];
    __shared__ float Ws[64][32];
    const int tid = threadIdx.x;
    const int tx = tid & 31, ty = tid >> 5;
    const int tok0 = blockIdx.x * 8;
    float acc = 0.f;

    for (int k0 = 0; k0 < CH; k0 += 64) {
        __syncthreads();
        if (tid < 128) {
            int t = tid >> 4, c4 = (tid & 15) * 4;
            *(float4*)&xs[t][c4] =
                *(const float4*)&x[(size_t)(tok0 + t) * CH + k0 + c4];
        }
        {
            int r = tid >> 2, c = (tid & 3) * 4;
            *(float4*)&Ws[r][c]      = *(const float4*)&WB[(size_t)(k0 + r) * SST + c];
            *(float4*)&Ws[r][16 + c] = *(const float4*)&WC[(size_t)(k0 + r) * SST + c];
        }
        __syncthreads();
        #pragma unroll
        for (int k = 0; k < 64; k++)
            acc = fmaf(xs[ty][k], Ws[k][tx], acc);
    }
    int tok = tok0 + ty;
    if (tx < 16) Bm[(size_t)tok * SST + tx] = acc;
    else         Cm[(size_t)tok * SST + (tx - 16)] = acc;
}

// ---------------- parallel scan, phase 1: per-chunk local state --------------
// grid (CH/64, NCH, BATCH), 64 threads; thread owns channel c within chunk.
__global__ __launch_bounds__(64)
void scan1_k(const float* __restrict__ xb, const float* __restrict__ dl,
             const float* __restrict__ Bm, const float* __restrict__ A_log,
             float* __restrict__ hloc, float* __restrict__ dsum)
{
    __shared__ float sB[SGRP * SST];
    const int tid = threadIdx.x;
    const int b = blockIdx.z, ck = blockIdx.y;
    const int c = blockIdx.x * 64 + tid;
    const int t0 = ck * CLEN;

    float A[SST];
    #pragma unroll
    for (int s = 0; s < SST; s++) A[s] = -expf(A_log[(size_t)c * SST + s]);
    float h[SST];
    #pragma unroll
    for (int s = 0; s < SST; s++) h[s] = 0.f;
    float Ds = 0.f;

    for (int g = 0; g < CLEN; g += SGRP) {
        const int tg = t0 + g;
        float rd[SGRP], rx[SGRP];
        size_t base = ((size_t)(b * SEQ + tg)) * CH + c;
        #pragma unroll
        for (int i = 0; i < SGRP; i++) {
            rd[i] = dl[base + (size_t)i * CH];
            rx[i] = xb[base + (size_t)i * CH];
        }
        __syncthreads();
        {
            size_t bb = ((size_t)(b * SEQ + tg)) * SST;
            ((float4*)sB)[tid] = ((const float4*)(Bm + bb))[tid];
        }
        __syncthreads();
        #pragma unroll
        for (int i = 0; i < SGRP; i++) {
            float d = rd[i];
            float dx = d * rx[i];
            Ds += d;
            #pragma unroll
            for (int s = 0; s < SST; s++) {
                float bar = __expf(d * A[s]);
                h[s] = fmaf(bar, h[s], dx * sB[i * SST + s]);
            }
        }
    }
    size_t o = (((size_t)(b * NCH + ck)) * CH + c) * SST;
    #pragma unroll
    for (int s4 = 0; s4 < SST; s4 += 4)
        *(float4*)&hloc[o + s4] = make_float4(h[s4], h[s4+1], h[s4+2], h[s4+3]);
    dsum[((size_t)(b * NCH + ck)) * CH + c] = Ds;
}

// ---------------- parallel scan, phase 2: combine chunk states ---------------
// grid (BATCH*CH/128), 128 threads; thread owns one (b,c) lane.
__global__ __launch_bounds__(128)
void scan2_k(const float* __restrict__ hloc, const float* __restrict__ dsum,
             const float* __restrict__ A_log, float* __restrict__ hin)
{
    const int lane = blockIdx.x * 128 + threadIdx.x;  // b*CH + c
    const int b = lane >> 10, c = lane & (CH - 1);

    float A[SST];
    #pragma unroll
    for (int s = 0; s < SST; s++) A[s] = -expf(A_log[(size_t)c * SST + s]);
    float h[SST];
    #pragma unroll
    for (int s = 0; s < SST; s++) h[s] = 0.f;

    for (int ck = 0; ck < NCH; ck++) {
        size_t o = (((size_t)(b * NCH + ck)) * CH + c) * SST;
        #pragma unroll
        for (int s4 = 0; s4 < SST; s4 += 4)
            *(float4*)&hin[o + s4] = make_float4(h[s4], h[s4+1], h[s4+2], h[s4+3]);
        float Ds = dsum[((size_t)(b * NCH + ck)) * CH + c];
        #pragma unroll
        for (int s4 = 0; s4 < SST; s4 += 4) {
            float4 hl = *(const float4*)&hloc[o + s4];
            h[s4+0] = fmaf(__expf(Ds * A[s4+0]), h[s4+0], hl.x);
            h[s4+1] = fmaf(__expf(Ds * A[s4+1]), h[s4+1], hl.y);
            h[s4+2] = fmaf(__expf(Ds * A[s4+2]), h[s4+2], hl.z);
            h[s4+3] = fmaf(__expf(Ds * A[s4+3]), h[s4+3], hl.w);
        }
    }
}

// ---------------- parallel scan, phase 3: rescan with real h_in, emit y ------
__global__ __launch_bounds__(64)
void scan3_k(const float* __restrict__ xb, const float* __restrict__ dl,
             const float* __restrict__ Bm, const float* __restrict__ Cm,
             const float* __restrict__ A_log, const float* __restrict__ hin,
             float* __restrict__ y)
{
    __shared__ float sB[SGRP * SST];
    __shared__ float sC[SGRP * SST];
    const int tid = threadIdx.x;
    const int b = blockIdx.z, ck = blockIdx.y;
    const int c = blockIdx.x * 64 + tid;
    const int t0 = ck * CLEN;

    float A[SST];
    #pragma unroll
    for (int s = 0; s < SST; s++) A[s] = -expf(A_log[(size_t)c * SST + s]);
    float h[SST];
    {
        size_t o = (((size_t)(b * NCH + ck)) * CH + c) * SST;
        #pragma unroll
        for (int s4 = 0; s4 < SST; s4 += 4) {
            float4 v = *(const float4*)&hin[o + s4];
            h[s4] = v.x; h[s4+1] = v.y; h[s4+2] = v.z; h[s4+3] = v.w;
        }
    }

    for (int g = 0; g < CLEN; g += SGRP) {
        const int tg = t0 + g;
        float rd[SGRP], rx[SGRP];
        size_t base = ((size_t)(b * SEQ + tg)) * CH + c;
        #pragma unroll
        for (int i = 0; i < SGRP; i++) {
            rd[i] = dl[base + (size_t)i * CH];
            rx[i] = xb[base + (size_t)i * CH];
        }
        __syncthreads();
        {
            size_t bb = ((size_t)(b * SEQ + tg)) * SST;
            ((float4*)sB)[tid] = ((const float4*)(Bm + bb))[tid];
            ((float4*)sC)[tid] = ((const float4*)(Cm + bb))[tid];
        }
        __syncthreads();
        #pragma unroll
        for (int i = 0; i < SGRP; i++) {
            float d = rd[i];
            float dx = d * rx[i];
            float yv = 0.f;
            #pragma unroll
            for (int s = 0; s < SST; s++) {
                float bar = __expf(d * A[s]);
                float hh = fmaf(bar, h[s], dx * sB[i * SST + s]);
                h[s] = hh;
                yv = fmaf(hh, sC[i * SST + s], yv);
            }
            y[base + (size_t)i * CH] = yv;
        }
    }
}

// ---------------- LayerNorm(x_base + y) -------------------------------------
__global__ __launch_bounds__(256)
void ln_k(const float* __restrict__ xb, const float* __restrict__ y,
          const float* __restrict__ gam, const float* __restrict__ bet,
          float* __restrict__ out)
{
    const int tok = blockIdx.x, tid = threadIdx.x;
    const float4* a4 = (const float4*)(xb + (size_t)tok * CH);
    const float4* b4 = (const float4*)(y  + (size_t)tok * CH);
    float4 v = a4[tid], w = b4[tid];
    v.x += w.x; v.y += w.y; v.z += w.z; v.w += w.w;
    float sum = v.x + v.y + v.z + v.w;
    float sq  = v.x * v.x + v.y * v.y + v.z * v.z + v.w * v.w;
    #pragma unroll
    for (int off = 16; off; off >>= 1) {
        sum += __shfl_xor_sync(0xffffffffu, sum, off);
        sq  += __shfl_xor_sync(0xffffffffu, sq,  off);
    }
    __shared__ float s1[8], s2[8];
    __shared__ float mu_s, rstd_s;
    if ((tid & 31) == 0) { s1[tid >> 5] = sum; s2[tid >> 5] = sq; }
    __syncthreads();
    if (tid == 0) {
        float t1 = 0.f, t2 = 0.f;
        #pragma unroll
        for (int i = 0; i < 8; i++) { t1 += s1[i]; t2 += s2[i]; }
        float mu = t1 * (1.f / CH);
        float var = t2 * (1.f / CH) - mu * mu;
        mu_s = mu;
        rstd_s = rsqrtf(var + 1e-5f);
    }
    __syncthreads();
    float mu = mu_s, rstd = rstd_s;
    float4 g = ((const float4*)gam)[tid];
    float4 be = ((const float4*)bet)[tid];
    float4 o;
    o.x = (v.x - mu) * rstd * g.x + be.x;
    o.y = (v.y - mu) * rstd * g.y + be.y;
    o.z = (v.z - mu) * rstd * g.z + be.z;
    o.w = (v.w - mu) * rstd * g.w + be.w;
    ((float4*)(out + (size_t)tok * CH))[tid] = o;
}

// ---------------- causal flash attention (fp32) ------------------------------
__global__ __launch_bounds__(256)
void flash_k(const float* __restrict__ Q, const float* __restrict__ K,
             const float* __restrict__ V, const float* __restrict__ temp,
             float* __restrict__ out)
{
    __shared__ float sQ[64 * 64];
    __shared__ float sKP[64 * 64];
    __shared__ float sV[64 * 64];

    const int tid = threadIdx.x;
    const int tx = tid & 15, ty = tid >> 4;
    const int qt = blockIdx.x, bh = blockIdx.y;
    const int b = bh >> 4, h = bh & 15;
    const int q0 = qt << 6;
    const float* Qg = Q + (size_t)bh * SEQ * HDIM;
    const float* Kg = K + (size_t)bh * SEQ * HDIM;
    const float* Vg = V + (size_t)bh * SEQ * HDIM;

    const float tv = temp[h];
    const float qk_scale = softplus_f(tv) * 0.125f;

    {
        const int r = tid >> 4;
        const int d4 = (tid & 15) << 2;
        #pragma unroll
        for (int rep = 0; rep < 4; rep++) {
            int rr = rep * 16 + r;
            float4 v = *(const float4*)&Qg[(size_t)(q0 + rr) * HDIM + d4];
            sQ[(d4 + 0) * 64 + rr] = v.x;
            sQ[(d4 + 1) * 64 + rr] = v.y;
            sQ[(d4 + 2) * 64 + rr] = v.z;
            sQ[(d4 + 3) * 64 + rr] = v.w;
        }
    }

    float o[4][4];
    #pragma unroll
    for (int a = 0; a < 4; a++)
        #pragma unroll
        for (int c = 0; c < 4; c++) o[a][c] = 0.f;
    float m[4] = {-1e30f, -1e30f, -1e30f, -1e30f};
    float l[4] = {0.f, 0.f, 0.f, 0.f};

    for (int kt = 0; kt <= qt; kt++) {
        const int k0 = kt << 6;
        __syncthreads();
        {
            const int r = tid >> 4;
            const int d4 = (tid & 15) << 2;
            #pragma unroll
            for (int rep = 0; rep < 4; rep++) {
                int rr = rep * 16 + r;
                float4 kv = *(const float4*)&Kg[(size_t)(k0 + rr) * HDIM + d4];
                sKP[(d4 + 0) * 64 + rr] = kv.x;
                sKP[(d4 + 1) * 64 + rr] = kv.y;
                sKP[(d4 + 2) * 64 + rr] = kv.z;
                sKP[(d4 + 3) * 64 + rr] = kv.w;
                float4 vv = *(const float4*)&Vg[(size_t)(k0 + rr) * HDIM + d4];
                *(float4*)&sV[rr * 64 + d4] = vv;
            }
        }
        __syncthreads();

        float s[4][4];
        #pragma unroll
        for (int a = 0; a < 4; a++)
            #pragma unroll
            for (int c = 0; c < 4; c++) s[a][c] = 0.f;
        #pragma unroll 16
        for (int d = 0; d < 64; d++) {
            float4 qa = *(const float4*)&sQ[d * 64 + ty * 4];
            float4 kb = *(const float4*)&sKP[d * 64 + tx * 4];
            s[0][0] = fmaf(qa.x, kb.x, s[0][0]); s[0][1] = fmaf(qa.x, kb.y, s[0][1]);
            s[0][2] = fmaf(qa.x, kb.z, s[0][2]); s[0][3] = fmaf(qa.x, kb.w, s[0][3]);
            s[1][0] = fmaf(qa.y, kb.x, s[1][0]); s[1][1] = fmaf(qa.y, kb.y, s[1][1]);
            s[1][2] = fmaf(qa.y, kb.z, s[1][2]); s[1][3] = fmaf(qa.y, kb.w, s[1][3]);
            s[2][0] = fmaf(qa.z, kb.x, s[2][0]); s[2][1] = fmaf(qa.z, kb.y, s[2][1]);
            s[2][2] = fmaf(qa.z, kb.z, s[2][2]); s[2][3] = fmaf(qa.z, kb.w, s[2][3]);
            s[3][0] = fmaf(qa.w, kb.x, s[3][0]); s[3][1] = fmaf(qa.w, kb.y, s[3][1]);
            s[3][2] = fmaf(qa.w, kb.z, s[3][2]); s[3][3] = fmaf(qa.w, kb.w, s[3][3]);
        }
        #pragma unroll
        for (int a = 0; a < 4; a++)
            #pragma unroll
            for (int c = 0; c < 4; c++) s[a][c] *= qk_scale;
        if (kt == qt) {
            #pragma unroll
            for (int a = 0; a < 4; a++)
                #pragma unroll
                for (int c = 0; c < 4; c++)
                    if (k0 + tx * 4 + c > q0 + ty * 4 + a) s[a][c] = -1e30f;
        }

        float fac[4];
        #pragma unroll
        for (int a = 0; a < 4; a++) {
            float rm = fmaxf(fmaxf(s[a][0], s[a][1]), fmaxf(s[a][2], s[a][3]));
            #pragma unroll
            for (int off = 1; off < 16; off <<= 1)
                rm = fmaxf(rm, __shfl_xor_sync(0xffffffffu, rm, off));
            float mnew = fmaxf(m[a], rm);
            fac[a] = __expf(m[a] - mnew);
            m[a] = mnew;
            float rs = 0.f;
            #pragma unroll
            for (int c = 0; c < 4; c++) {
                float pv = __expf(s[a][c] - mnew);
                s[a][c] = pv;
                rs += pv;
            }
            #pragma unroll
            for (int off = 1; off < 16; off <<= 1)
                rs += __shfl_xor_sync(0xffffffffu, rs, off);
            l[a] = l[a] * fac[a] + rs;
        }
        #pragma unroll
        for (int a = 0; a < 4; a++)
            #pragma unroll
            for (int c = 0; c < 4; c++) o[a][c] *= fac[a];

        __syncthreads();
        #pragma unroll
        for (int c = 0; c < 4; c++) {
            float4 pv = make_float4(s[0][c], s[1][c], s[2][c], s[3][c]);
            *(float4*)&sKP[(tx * 4 + c) * 64 + ty * 4] = pv;
        }
        __syncthreads();

        #pragma unroll 16
        for (int jj = 0; jj < 64; jj++) {
            float4 pa = *(const float4*)&sKP[jj * 64 + ty * 4];
            float4 vb = *(const float4*)&sV[jj * 64 + tx * 4];
            o[0][0] = fmaf(pa.x, vb.x, o[0][0]); o[0][1] = fmaf(pa.x, vb.y, o[0][1]);
            o[0][2] = fmaf(pa.x, vb.z, o[0][2]); o[0][3] = fmaf(pa.x, vb.w, o[0][3]);
            o[1][0] = fmaf(pa.y, vb.x, o[1][0]); o[1][1] = fmaf(pa.y, vb.y, o[1][1]);
            o[1][2] = fmaf(pa.y, vb.z, o[1][2]); o[1][3] = fmaf(pa.y, vb.w, o[1][3]);
            o[2][0] = fmaf(pa.z, vb.x, o[2][0]); o[2][1] = fmaf(pa.z, vb.y, o[2][1]);
            o[2][2] = fmaf(pa.z, vb.z, o[2][2]); o[2][3] = fmaf(pa.z, vb.w, o[2][3]);
            o[3][0] = fmaf(pa.w, vb.x, o[3][0]); o[3][1] = fmaf(pa.w, vb.y, o[3][1]);
            o[3][2] = fmaf(pa.w, vb.z, o[3][2]); o[3][3] = fmaf(pa.w, vb.w, o[3][3]);
        }
    }

    #pragma unroll
    for (int a = 0; a < 4; a++) {
        float inv = 1.f / l[a];
        int qrow = q0 + ty * 4 + a;
        float4 v = make_float4(o[a][0] * inv, o[a][1] * inv,
                               o[a][2] * inv, o[a][3] * inv);
        *(float4*)&out[((size_t)(b * SEQ + qrow)) * CH + h * HDIM + tx * 4] = v;
    }
}

// ---------------- launcher ---------------------------------------------------
extern "C" void kernel_launch(void* const* d_in, const int* in_sizes, int n_in,
                              void* d_out, int out_size)
{
    const float* x     = (const float*)d_in[0];
    const float* A_log = (const float*)d_in[1];
    const float* Wd    = (const float*)d_in[2];
    const float* bd    = (const float*)d_in[3];
    const float* WB    = (const float*)d_in[4];
    const float* WC    = (const float*)d_in[5];
    const float* Wq    = (const float*)d_in[6];
    const float* bq    = (const float*)d_in[7];
    const float* Wk    = (const float*)d_in[8];
    const float* bk    = (const float*)d_in[9];
    const float* Wv    = (const float*)d_in[10];
    const float* bv    = (const float*)d_in[11];
    const float* Wx    = (const float*)d_in[12];
    const float* bx    = (const float*)d_in[13];
    const float* Wo    = (const float*)d_in[14];
    const float* bo    = (const float*)d_in[15];
    const float* ln_g  = (const float*)d_in[16];
    const float* ln_b  = (const float*)d_in[17];
    const float* temp  = (const float*)d_in[18];
    float* out = (float*)d_out;

    float* xb = nullptr; cudaGetSymbolAddress((void**)&xb, g_xb);
    float* dl = nullptr; cudaGetSymbolAddress((void**)&dl, g_dl);
    float* Bm = nullptr; cudaGetSymbolAddress((void**)&Bm, g_Bm);
    float* Cm = nullptr; cudaGetSymbolAddress((void**)&Cm, g_Cm);
    float* yb = nullptr; cudaGetSymbolAddress((void**)&yb, g_y);
    float* hy = nullptr; cudaGetSymbolAddress((void**)&hy, g_hy);
    float* Qb = nullptr; cudaGetSymbolAddress((void**)&Qb, g_Q);
    float* Kb = nullptr; cudaGetSymbolAddress((void**)&Kb, g_K);
    float* Vb = nullptr; cudaGetSymbolAddress((void**)&Vb, g_V);
    float* at = nullptr; cudaGetSymbolAddress((void**)&at, g_at);
    float* hloc = nullptr; cudaGetSymbolAddress((void**)&hloc, g_hloc);
    float* hin  = nullptr; cudaGetSymbolAddress((void**)&hin,  g_hin);
    float* dsum = nullptr; cudaGetSymbolAddress((void**)&dsum, g_dsum);

    dim3 gemm_grid(CH / 128, NTOK / 128);

    sgemm_k<<<gemm_grid, 256>>>(x, Wx, bx, xb, NTOK, CH, CH, 0);
    sgemm_k<<<gemm_grid, 256>>>(x, Wd, bd, dl, NTOK, CH, CH, 1);
    bc_k<<<NTOK / 8, 256>>>(x, WB, WC, Bm, Cm);

    dim3 scan_grid(CH / 64, NCH, BATCH);
    scan1_k<<<scan_grid, 64>>>(xb, dl, Bm, A_log, hloc, dsum);
    scan2_k<<<BATCH * CH / 128, 128>>>(hloc, dsum, A_log, hin);
    scan3_k<<<scan_grid, 64>>>(xb, dl, Bm, Cm, A_log, hin, yb);

    ln_k<<<NTOK, 256>>>(xb, yb, ln_g, ln_b, hy);
    sgemm_k<<<gemm_grid, 256>>>(hy, Wq, bq, Qb, NTOK, CH, CH, 2);
    sgemm_k<<<gemm_grid, 256>>>(hy, Wk, bk, Kb, NTOK, CH, CH, 2);
    sgemm_k<<<gemm_grid, 256>>>(hy, Wv, bv, Vb, NTOK, CH, CH, 2);
    flash_k<<<dim3(SEQ / 64, BATCH * NH), 256>>>(Qb, Kb, Vb, temp, at);
    sgemm_k<<<gemm_grid, 256>>>(at, Wo, bo, out, NTOK, CH, CH, 0);
}

// round 5
// speedup vs baseline: 1.7209x; 1.5118x over previous
#include <cuda_runtime.h>
#include <cuda_bf16.h>
#include <cstdint>
#include <cmath>

#define BATCH 2
#define SEQ   2048
#define CH    1024
#define NH    16
#define SST   16
#define HDIM  64
#define NTOK  (BATCH*SEQ)   // 4096

#define NCH   32            // time chunks for parallel scan
#define CLEN  (SEQ/NCH)     // 64 steps per chunk
#define SGRP  16            // staging group (steps)

// ---------------- device scratch (allocation-free) --------------------------
__device__ float g_xb[(size_t)NTOK*CH];
__device__ float g_dl[(size_t)NTOK*CH];
__device__ float g_Bm[(size_t)NTOK*SST];
__device__ float g_Cm[(size_t)NTOK*SST];
__device__ float g_y [(size_t)NTOK*CH];
__device__ float g_hy[(size_t)NTOK*CH];
__device__ float g_Q [(size_t)NTOK*CH];   // (B,H,T,HD)
__device__ float g_K [(size_t)NTOK*CH];
__device__ float g_V [(size_t)NTOK*CH];
__device__ float g_at[(size_t)NTOK*CH];   // attention out, (B,T,C)
// parallel-scan intermediates
__device__ float g_hloc[(size_t)BATCH*NCH*CH*SST];
__device__ float g_hin [(size_t)BATCH*NCH*CH*SST];
__device__ float g_dsum[(size_t)BATCH*NCH*CH];
// bf16 split activations + transposed split weights
__device__ __nv_bfloat16 g_ahi[(size_t)NTOK*CH];
__device__ __nv_bfloat16 g_alo[(size_t)NTOK*CH];
__device__ __nv_bfloat16 g_wt [(size_t)12*CH*CH];  // 6 weights x {hi,lo}, [N][K]

__device__ __forceinline__ float softplus_f(float x) {
    return (x > 20.f) ? x : log1pf(expf(x));
}

__device__ __forceinline__ uint32_t s2u(const void* p) {
    uint32_t a;
    asm("{ .reg .u64 t; cvta.to.shared.u64 t, %1; cvt.u32.u64 %0, t; }"
        : "=r"(a) : "l"(p));
    return a;
}

#define CP_ASYNC16(saddr, gptr) \
    asm volatile("cp.async.cg.shared.global [%0], [%1], 16;" \
                 :: "r"(saddr), "l"(gptr))
#define CP_COMMIT()  asm volatile("cp.async.commit_group;")
#define CP_WAIT1()   asm volatile("cp.async.wait_group 1;")
#define CP_WAIT0()   asm volatile("cp.async.wait_group 0;")

#define LDSM4(R0, R1, R2, R3, addr) \
    asm volatile("ldmatrix.sync.aligned.m8n8.x4.shared.b16 {%0,%1,%2,%3}, [%4];" \
                 : "=r"(R0), "=r"(R1), "=r"(R2), "=r"(R3) : "r"(addr))

#define MMA16816(C, A0, A1, A2, A3, B0, B1) \
    asm volatile("mma.sync.aligned.m16n8k16.row.col.f32.bf16.bf16.f32 " \
                 "{%0,%1,%2,%3}, {%4,%5,%6,%7}, {%8,%9}, {%0,%1,%2,%3};" \
                 : "+f"((C)[0]), "+f"((C)[1]), "+f"((C)[2]), "+f"((C)[3]) \
                 : "r"(A0), "r"(A1), "r"(A2), "r"(A3), "r"(B0), "r"(B1))

// ============================================================================
// bf16-split tensor-core GEMM: out[4096,1024] = A @ W^T (+bias)
// A split: Ahi/Alo [M][K] row-major.  W split+transposed: Bhi/Blo [N][K].
// D = Ahi*Bhi + Ahi*Blo + Alo*Bhi, fp32 accum (mma.sync m16n8k16 bf16).
// CTA tile 128x128, K chunks of 32, double-buffered smem via cp.async.
// SMEM tile rows padded to 40 bf16 (80B) -> conflict-free ldmatrix.
// flags bit0: softplus epilogue.  bit1: (B,H,T,HD) head layout.
// ============================================================================
#define TPAD   40                       // bf16 per padded row
#define TROWB  (TPAD*2)                 // 80 bytes
#define TILE_B (128*TROWB)              // 10240 bytes per tile
#define STG_B  (4*TILE_B)               // 40960 per stage (Ah, Al, Bh, Bl)
#define MM_SMEM (2*STG_B)               // 81920

__global__ __launch_bounds__(256, 2)
void mm_bf16(const __nv_bfloat16* __restrict__ Ahi,
             const __nv_bfloat16* __restrict__ Alo,
             const __nv_bfloat16* __restrict__ Bhi,
             const __nv_bfloat16* __restrict__ Blo,
             const float* __restrict__ bias, float* __restrict__ out,
             int flags)
{
    extern __shared__ char smem[];
    const int tid  = threadIdx.x;
    const int wid  = tid >> 5, lane = tid & 31;
    const int m0 = blockIdx.y << 7, n0 = blockIdx.x << 7;
    const int wm = wid & 1, wn = wid >> 1;   // warp: rows wm*64.., cols wn*32..
    const uint32_t sbase = s2u(smem);

    // cp.async slot mapping: per tile 512 x 16B slots, 2 per thread
    const int r0s = tid >> 2,         sg0 = tid & 3;
    const int r1s = r0s + 64,         sg1 = sg0;
    const uint32_t d0 = r0s * TROWB + sg0 * 16;
    const uint32_t d1 = r1s * TROWB + sg1 * 16;

    const __nv_bfloat16* tp[4] = {Ahi, Alo, Bhi, Blo};

    float acc[4][4][4];
    #pragma unroll
    for (int i = 0; i < 4; i++)
        #pragma unroll
        for (int j = 0; j < 4; j++)
            #pragma unroll
            for (int q = 0; q < 4; q++) acc[i][j][q] = 0.f;

    // ldmatrix lane offsets
    // A (m16k16 .x4): row = wm*64 + i*16 + lane%16, kbyte = (lane/16)*16
    const uint32_t aoff = (uint32_t)(wm * 64 + (lane & 15)) * TROWB
                        + ((lane >> 4) & 1) * 16;
    // B (two n-tiles per .x4): g=lane>>3: row = wn*32 + (g>>1)*8 + lane%8,
    //                          kbyte = (g&1)*16
    const uint32_t boff = (uint32_t)(wn * 32 + ((lane >> 4) & 1) * 8 + (lane & 7)) * TROWB
                        + ((lane >> 3) & 1) * 16;

    // ---- prologue: issue chunk 0
    {
        const int k0 = 0;
        const uint32_t sb = sbase;
        #pragma unroll
        for (int t = 0; t < 4; t++) {
            const int rb = (t < 2) ? m0 : n0;
            const __nv_bfloat16* g = tp[t];
            CP_ASYNC16(sb + t * TILE_B + d0,
                       g + (size_t)(rb + r0s) * CH + k0 + sg0 * 8);
            CP_ASYNC16(sb + t * TILE_B + d1,
                       g + (size_t)(rb + r1s) * CH + k0 + sg1 * 8);
        }
        CP_COMMIT();
    }

    const int NC = CH / 32;   // 32 chunks
    for (int ck = 0; ck < NC; ck++) {
        if (ck + 1 < NC) {
            const int k0 = (ck + 1) << 5;
            const uint32_t sb = sbase + ((ck + 1) & 1) * STG_B;
            #pragma unroll
            for (int t = 0; t < 4; t++) {
                const int rb = (t < 2) ? m0 : n0;
                const __nv_bfloat16* g = tp[t];
                CP_ASYNC16(sb + t * TILE_B + d0,
                           g + (size_t)(rb + r0s) * CH + k0 + sg0 * 8);
                CP_ASYNC16(sb + t * TILE_B + d1,
                           g + (size_t)(rb + r1s) * CH + k0 + sg1 * 8);
            }
            CP_COMMIT();
            CP_WAIT1();
        } else {
            CP_WAIT0();
        }
        __syncthreads();

        const uint32_t sb = sbase + (ck & 1) * STG_B;
        #pragma unroll
        for (int ks = 0; ks < 2; ks++) {
            const uint32_t ka  = sb + aoff + ks * 32;               // A-hi
            const uint32_t ka2 = ka + TILE_B;                       // A-lo
            const uint32_t kb  = sb + 2 * TILE_B + boff + ks * 32;  // B-hi
            const uint32_t kb2 = kb + TILE_B;                       // B-lo

            uint32_t a[4][4], bh[2][4], bl[2][4];
            #pragma unroll
            for (int i = 0; i < 4; i++)
                LDSM4(a[i][0], a[i][1], a[i][2], a[i][3], ka + i * 16 * TROWB);
            #pragma unroll
            for (int j = 0; j < 2; j++)
                LDSM4(bh[j][0], bh[j][1], bh[j][2], bh[j][3], kb + j * 16 * TROWB);
            // term 1: Ahi * Bhi
            #pragma unroll
            for (int i = 0; i < 4; i++)
                #pragma unroll
                for (int jj = 0; jj < 4; jj++)
                    MMA16816(acc[i][jj], a[i][0], a[i][1], a[i][2], a[i][3],
                             bh[jj >> 1][(jj & 1) * 2], bh[jj >> 1][(jj & 1) * 2 + 1]);
            #pragma unroll
            for (int j = 0; j < 2; j++)
                LDSM4(bl[j][0], bl[j][1], bl[j][2], bl[j][3], kb2 + j * 16 * TROWB);
            // term 2: Ahi * Blo
            #pragma unroll
            for (int i = 0; i < 4; i++)
                #pragma unroll
                for (int jj = 0; jj < 4; jj++)
                    MMA16816(acc[i][jj], a[i][0], a[i][1], a[i][2], a[i][3],
                             bl[jj >> 1][(jj & 1) * 2], bl[jj >> 1][(jj & 1) * 2 + 1]);
            #pragma unroll
            for (int i = 0; i < 4; i++)
                LDSM4(a[i][0], a[i][1], a[i][2], a[i][3], ka2 + i * 16 * TROWB);
            // term 3: Alo * Bhi
            #pragma unroll
            for (int i = 0; i < 4; i++)
                #pragma unroll
                for (int jj = 0; jj < 4; jj++)
                    MMA16816(acc[i][jj], a[i][0], a[i][1], a[i][2], a[i][3],
                             bh[jj >> 1][(jj & 1) * 2], bh[jj >> 1][(jj & 1) * 2 + 1]);
        }
        __syncthreads();
    }

    // ---- epilogue: C fragment c0,c1 at (row, col..col+1); c2,c3 at row+8
    #pragma unroll
    for (int i = 0; i < 4; i++) {
        #pragma unroll
        for (int jj = 0; jj < 4; jj++) {
            const int row = m0 + wm * 64 + i * 16 + (lane >> 2);
            const int col = n0 + wn * 32 + jj * 8 + (lane & 3) * 2;
            float b0 = bias[col], b1 = bias[col + 1];
            float v0 = acc[i][jj][0] + b0, v1 = acc[i][jj][1] + b1;
            float v2 = acc[i][jj][2] + b0, v3 = acc[i][jj][3] + b1;
            if (flags & 1) {
                v0 = softplus_f(v0); v1 = softplus_f(v1);
                v2 = softplus_f(v2); v3 = softplus_f(v3);
            }
            if (flags & 2) {
                const int hh = col >> 6, hd = col & (HDIM - 1);
                const int bb0 = row >> 11, t0 = row & (SEQ - 1);
                size_t base0 = ((((size_t)bb0 * NH + hh) * SEQ) + t0) * HDIM + hd;
                *(float2*)(out + base0) = make_float2(v0, v1);
                const int r8 = row + 8;
                const int bb1 = r8 >> 11, t1 = r8 & (SEQ - 1);
                size_t base1 = ((((size_t)bb1 * NH + hh) * SEQ) + t1) * HDIM + hd;
                *(float2*)(out + base1) = make_float2(v2, v3);
            } else {
                *(float2*)(out + (size_t)row * CH + col)       = make_float2(v0, v1);
                *(float2*)(out + (size_t)(row + 8) * CH + col) = make_float2(v2, v3);
            }
        }
    }
}

// ---------------- fp32 -> bf16 hi/lo split (activations) --------------------
__global__ __launch_bounds__(256)
void cvt_act(const float* __restrict__ in, __nv_bfloat16* __restrict__ hi,
             __nv_bfloat16* __restrict__ lo)
{
    size_t i = ((size_t)blockIdx.x * 256 + threadIdx.x) * 4;
    float4 v = *(const float4*)(in + i);
    __nv_bfloat16 h0 = __float2bfloat16(v.x);
    __nv_bfloat16 h1 = __float2bfloat16(v.y);
    __nv_bfloat16 h2 = __float2bfloat16(v.z);
    __nv_bfloat16 h3 = __float2bfloat16(v.w);
    __nv_bfloat16 l0 = __float2bfloat16(v.x - __bfloat162float(h0));
    __nv_bfloat16 l1 = __float2bfloat16(v.y - __bfloat162float(h1));
    __nv_bfloat16 l2 = __float2bfloat16(v.z - __bfloat162float(h2));
    __nv_bfloat16 l3 = __float2bfloat16(v.w - __bfloat162float(h3));
    __nv_bfloat162* h2p = (__nv_bfloat162*)(hi + i);
    __nv_bfloat162* l2p = (__nv_bfloat162*)(lo + i);
    h2p[0] = __nv_bfloat162(h0, h1); h2p[1] = __nv_bfloat162(h2, h3);
    l2p[0] = __nv_bfloat162(l0, l1); l2p[1] = __nv_bfloat162(l2, l3);
}

// ---------------- weight transpose + hi/lo split: W[K][N] -> T[N][K] --------
__global__ __launch_bounds__(256)
void cvt_wt(const float* __restrict__ W, __nv_bfloat16* __restrict__ Th,
            __nv_bfloat16* __restrict__ Tl)
{
    __shared__ float t[32][33];
    int tx = threadIdx.x, ty = threadIdx.y;
    int nb = blockIdx.x * 32, kb = blockIdx.y * 32;
    #pragma unroll
    for (int j = 0; j < 32; j += 8)
        t[ty + j][tx] = W[(size_t)(kb + ty + j) * CH + nb + tx];
    __syncthreads();
    #pragma unroll
    for (int j = 0; j < 32; j += 8) {
        float v = t[tx][ty + j];
        __nv_bfloat16 h = __float2bfloat16(v);
        __nv_bfloat16 l = __float2bfloat16(v - __bfloat162float(h));
        size_t o = (size_t)(nb + ty + j) * CH + kb + tx;
        Th[o] = h; Tl[o] = l;
    }
}

// ---------------- small B/C projection ---------------------------------------
__global__ __launch_bounds__(256)
void bc_k(const float* __restrict__ x, const float* __restrict__ WB,
          const float* __restrict__ WC, float* __restrict__ Bm,
          float* __restrict__ Cm)
{
    __shared__ float xs[8][64];
    __shared__ float Ws[64][32];
    const int tid = threadIdx.x;
    const int tx = tid & 31, ty = tid >> 5;
    const int tok0 = blockIdx.x * 8;
    float acc = 0.f;

    for (int k0 = 0; k0 < CH; k0 += 64) {
        __syncthreads();
        if (tid < 128) {
            int t = tid >> 4, c4 = (tid & 15) * 4;
            *(float4*)&xs[t][c4] =
                *(const float4*)&x[(size_t)(tok0 + t) * CH + k0 + c4];
        }
        {
            int r = tid >> 2, c = (tid & 3) * 4;
            *(float4*)&Ws[r][c]      = *(const float4*)&WB[(size_t)(k0 + r) * SST + c];
            *(float4*)&Ws[r][16 + c] = *(const float4*)&WC[(size_t)(k0 + r) * SST + c];
        }
        __syncthreads();
        #pragma unroll
        for (int k = 0; k < 64; k++)
            acc = fmaf(xs[ty][k], Ws[k][tx], acc);
    }
    int tok = tok0 + ty;
    if (tx < 16) Bm[(size_t)tok * SST + tx] = acc;
    else         Cm[(size_t)tok * SST + (tx - 16)] = acc;
}

// ---------------- parallel scan, phase 1 -------------------------------------
__global__ __launch_bounds__(64)
void scan1_k(const float* __restrict__ xb, const float* __restrict__ dl,
             const float* __restrict__ Bm, const float* __restrict__ A_log,
             float* __restrict__ hloc, float* __restrict__ dsum)
{
    __shared__ float sB[SGRP * SST];
    const int tid = threadIdx.x;
    const int b = blockIdx.z, ck = blockIdx.y;
    const int c = blockIdx.x * 64 + tid;
    const int t0 = ck * CLEN;

    float A[SST];
    #pragma unroll
    for (int s = 0; s < SST; s++) A[s] = -expf(A_log[(size_t)c * SST + s]);
    float h[SST];
    #pragma unroll
    for (int s = 0; s < SST; s++) h[s] = 0.f;
    float Ds = 0.f;

    for (int g = 0; g < CLEN; g += SGRP) {
        const int tg = t0 + g;
        float rd[SGRP], rx[SGRP];
        size_t base = ((size_t)(b * SEQ + tg)) * CH + c;
        #pragma unroll
        for (int i = 0; i < SGRP; i++) {
            rd[i] = dl[base + (size_t)i * CH];
            rx[i] = xb[base + (size_t)i * CH];
        }
        __syncthreads();
        {
            size_t bb = ((size_t)(b * SEQ + tg)) * SST;
            ((float4*)sB)[tid] = ((const float4*)(Bm + bb))[tid];
        }
        __syncthreads();
        #pragma unroll
        for (int i = 0; i < SGRP; i++) {
            float d = rd[i];
            float dx = d * rx[i];
            Ds += d;
            #pragma unroll
            for (int s = 0; s < SST; s++) {
                float bar = __expf(d * A[s]);
                h[s] = fmaf(bar, h[s], dx * sB[i * SST + s]);
            }
        }
    }
    size_t o = (((size_t)(b * NCH + ck)) * CH + c) * SST;
    #pragma unroll
    for (int s4 = 0; s4 < SST; s4 += 4)
        *(float4*)&hloc[o + s4] = make_float4(h[s4], h[s4+1], h[s4+2], h[s4+3]);
    dsum[((size_t)(b * NCH + ck)) * CH + c] = Ds;
}

// ---------------- parallel scan, phase 2 -------------------------------------
__global__ __launch_bounds__(128)
void scan2_k(const float* __restrict__ hloc, const float* __restrict__ dsum,
             const float* __restrict__ A_log, float* __restrict__ hin)
{
    const int lane = blockIdx.x * 128 + threadIdx.x;
    const int b = lane >> 10, c = lane & (CH - 1);

    float A[SST];
    #pragma unroll
    for (int s = 0; s < SST; s++) A[s] = -expf(A_log[(size_t)c * SST + s]);
    float h[SST];
    #pragma unroll
    for (int s = 0; s < SST; s++) h[s] = 0.f;

    for (int ck = 0; ck < NCH; ck++) {
        size_t o = (((size_t)(b * NCH + ck)) * CH + c) * SST;
        #pragma unroll
        for (int s4 = 0; s4 < SST; s4 += 4)
            *(float4*)&hin[o + s4] = make_float4(h[s4], h[s4+1], h[s4+2], h[s4+3]);
        float Ds = dsum[((size_t)(b * NCH + ck)) * CH + c];
        #pragma unroll
        for (int s4 = 0; s4 < SST; s4 += 4) {
            float4 hl = *(const float4*)&hloc[o + s4];
            h[s4+0] = fmaf(__expf(Ds * A[s4+0]), h[s4+0], hl.x);
            h[s4+1] = fmaf(__expf(Ds * A[s4+1]), h[s4+1], hl.y);
            h[s4+2] = fmaf(__expf(Ds * A[s4+2]), h[s4+2], hl.z);
            h[s4+3] = fmaf(__expf(Ds * A[s4+3]), h[s4+3], hl.w);
        }
    }
}

// ---------------- parallel scan, phase 3 -------------------------------------
__global__ __launch_bounds__(64)
void scan3_k(const float* __restrict__ xb, const float* __restrict__ dl,
             const float* __restrict__ Bm, const float* __restrict__ Cm,
             const float* __restrict__ A_log, const float* __restrict__ hin,
             float* __restrict__ y)
{
    __shared__ float sB[SGRP * SST];
    __shared__ float sC[SGRP * SST];
    const int tid = threadIdx.x;
    const int b = blockIdx.z, ck = blockIdx.y;
    const int c = blockIdx.x * 64 + tid;
    const int t0 = ck * CLEN;

    float A[SST];
    #pragma unroll
    for (int s = 0; s < SST; s++) A[s] = -expf(A_log[(size_t)c * SST + s]);
    float h[SST];
    {
        size_t o = (((size_t)(b * NCH + ck)) * CH + c) * SST;
        #pragma unroll
        for (int s4 = 0; s4 < SST; s4 += 4) {
            float4 v = *(const float4*)&hin[o + s4];
            h[s4] = v.x; h[s4+1] = v.y; h[s4+2] = v.z; h[s4+3] = v.w;
        }
    }

    for (int g = 0; g < CLEN; g += SGRP) {
        const int tg = t0 + g;
        float rd[SGRP], rx[SGRP];
        size_t base = ((size_t)(b * SEQ + tg)) * CH + c;
        #pragma unroll
        for (int i = 0; i < SGRP; i++) {
            rd[i] = dl[base + (size_t)i * CH];
            rx[i] = xb[base + (size_t)i * CH];
        }
        __syncthreads();
        {
            size_t bb = ((size_t)(b * SEQ + tg)) * SST;
            ((float4*)sB)[tid] = ((const float4*)(Bm + bb))[tid];
            ((float4*)sC)[tid] = ((const float4*)(Cm + bb))[tid];
        }
        __syncthreads();
        #pragma unroll
        for (int i = 0; i < SGRP; i++) {
            float d = rd[i];
            float dx = d * rx[i];
            float yv = 0.f;
            #pragma unroll
            for (int s = 0; s < SST; s++) {
                float bar = __expf(d * A[s]);
                float hh = fmaf(bar, h[s], dx * sB[i * SST + s]);
                h[s] = hh;
                yv = fmaf(hh, sC[i * SST + s], yv);
            }
            y[base + (size_t)i * CH] = yv;
        }
    }
}

// ---------------- LayerNorm(x_base + y) -------------------------------------
__global__ __launch_bounds__(256)
void ln_k(const float* __restrict__ xb, const float* __restrict__ y,
          const float* __restrict__ gam, const float* __restrict__ bet,
          float* __restrict__ out)
{
    const int tok = blockIdx.x, tid = threadIdx.x;
    const float4* a4 = (const float4*)(xb + (size_t)tok * CH);
    const float4* b4 = (const float4*)(y  + (size_t)tok * CH);
    float4 v = a4[tid], w = b4[tid];
    v.x += w.x; v.y += w.y; v.z += w.z; v.w += w.w;
    float sum = v.x + v.y + v.z + v.w;
    float sq  = v.x * v.x + v.y * v.y + v.z * v.z + v.w * v.w;
    #pragma unroll
    for (int off = 16; off; off >>= 1) {
        sum += __shfl_xor_sync(0xffffffffu, sum, off);
        sq  += __shfl_xor_sync(0xffffffffu, sq,  off);
    }
    __shared__ float s1[8], s2[8];
    __shared__ float mu_s, rstd_s;
    if ((tid & 31) == 0) { s1[tid >> 5] = sum; s2[tid >> 5] = sq; }
    __syncthreads();
    if (tid == 0) {
        float t1 = 0.f, t2 = 0.f;
        #pragma unroll
        for (int i = 0; i < 8; i++) { t1 += s1[i]; t2 += s2[i]; }
        float mu = t1 * (1.f / CH);
        float var = t2 * (1.f / CH) - mu * mu;
        mu_s = mu;
        rstd_s = rsqrtf(var + 1e-5f);
    }
    __syncthreads();
    float mu = mu_s, rstd = rstd_s;
    float4 g = ((const float4*)gam)[tid];
    float4 be = ((const float4*)bet)[tid];
    float4 o;
    o.x = (v.x - mu) * rstd * g.x + be.x;
    o.y = (v.y - mu) * rstd * g.y + be.y;
    o.z = (v.z - mu) * rstd * g.z + be.z;
    o.w = (v.w - mu) * rstd * g.w + be.w;
    ((float4*)(out + (size_t)tok * CH))[tid] = o;
}

// ---------------- causal flash attention (fp32) ------------------------------
__global__ __launch_bounds__(256)
void flash_k(const float* __restrict__ Q, const float* __restrict__ K,
             const float* __restrict__ V, const float* __restrict__ temp,
             float* __restrict__ out)
{
    __shared__ float sQ[64 * 64];
    __shared__ float sKP[64 * 64];
    __shared__ float sV[64 * 64];

    const int tid = threadIdx.x;
    const int tx = tid & 15, ty = tid >> 4;
    const int qt = blockIdx.x, bh = blockIdx.y;
    const int b = bh >> 4, h = bh & 15;
    const int q0 = qt << 6;
    const float* Qg = Q + (size_t)bh * SEQ * HDIM;
    const float* Kg = K + (size_t)bh * SEQ * HDIM;
    const float* Vg = V + (size_t)bh * SEQ * HDIM;

    const float tv = temp[h];
    const float qk_scale = softplus_f(tv) * 0.125f;

    {
        const int r = tid >> 4;
        const int d4 = (tid & 15) << 2;
        #pragma unroll
        for (int rep = 0; rep < 4; rep++) {
            int rr = rep * 16 + r;
            float4 v = *(const float4*)&Qg[(size_t)(q0 + rr) * HDIM + d4];
            sQ[(d4 + 0) * 64 + rr] = v.x;
            sQ[(d4 + 1) * 64 + rr] = v.y;
            sQ[(d4 + 2) * 64 + rr] = v.z;
            sQ[(d4 + 3) * 64 + rr] = v.w;
        }
    }

    float o[4][4];
    #pragma unroll
    for (int a = 0; a < 4; a++)
        #pragma unroll
        for (int c = 0; c < 4; c++) o[a][c] = 0.f;
    float m[4] = {-1e30f, -1e30f, -1e30f, -1e30f};
    float l[4] = {0.f, 0.f, 0.f, 0.f};

    for (int kt = 0; kt <= qt; kt++) {
        const int k0 = kt << 6;
        __syncthreads();
        {
            const int r = tid >> 4;
            const int d4 = (tid & 15) << 2;
            #pragma unroll
            for (int rep = 0; rep < 4; rep++) {
                int rr = rep * 16 + r;
                float4 kv = *(const float4*)&Kg[(size_t)(k0 + rr) * HDIM + d4];
                sKP[(d4 + 0) * 64 + rr] = kv.x;
                sKP[(d4 + 1) * 64 + rr] = kv.y;
                sKP[(d4 + 2) * 64 + rr] = kv.z;
                sKP[(d4 + 3) * 64 + rr] = kv.w;
                float4 vv = *(const float4*)&Vg[(size_t)(k0 + rr) * HDIM + d4];
                *(float4*)&sV[rr * 64 + d4] = vv;
            }
        }
        __syncthreads();

        float s[4][4];
        #pragma unroll
        for (int a = 0; a < 4; a++)
            #pragma unroll
            for (int c = 0; c < 4; c++) s[a][c] = 0.f;
        #pragma unroll 16
        for (int d = 0; d < 64; d++) {
            float4 qa = *(const float4*)&sQ[d * 64 + ty * 4];
            float4 kb = *(const float4*)&sKP[d * 64 + tx * 4];
            s[0][0] = fmaf(qa.x, kb.x, s[0][0]); s[0][1] = fmaf(qa.x, kb.y, s[0][1]);
            s[0][2] = fmaf(qa.x, kb.z, s[0][2]); s[0][3] = fmaf(qa.x, kb.w, s[0][3]);
            s[1][0] = fmaf(qa.y, kb.x, s[1][0]); s[1][1] = fmaf(qa.y, kb.y, s[1][1]);
            s[1][2] = fmaf(qa.y, kb.z, s[1][2]); s[1][3] = fmaf(qa.y, kb.w, s[1][3]);
            s[2][0] = fmaf(qa.z, kb.x, s[2][0]); s[2][1] = fmaf(qa.z, kb.y, s[2][1]);
            s[2][2] = fmaf(qa.z, kb.z, s[2][2]); s[2][3] = fmaf(qa.z, kb.w, s[2][3]);
            s[3][0] = fmaf(qa.w, kb.x, s[3][0]); s[3][1] = fmaf(qa.w, kb.y, s[3][1]);
            s[3][2] = fmaf(qa.w, kb.z, s[3][2]); s[3][3] = fmaf(qa.w, kb.w, s[3][3]);
        }
        #pragma unroll
        for (int a = 0; a < 4; a++)
            #pragma unroll
            for (int c = 0; c < 4; c++) s[a][c] *= qk_scale;
        if (kt == qt) {
            #pragma unroll
            for (int a = 0; a < 4; a++)
                #pragma unroll
                for (int c = 0; c < 4; c++)
                    if (k0 + tx * 4 + c > q0 + ty * 4 + a) s[a][c] = -1e30f;
        }

        float fac[4];
        #pragma unroll
        for (int a = 0; a < 4; a++) {
            float rm = fmaxf(fmaxf(s[a][0], s[a][1]), fmaxf(s[a][2], s[a][3]));
            #pragma unroll
            for (int off = 1; off < 16; off <<= 1)
                rm = fmaxf(rm, __shfl_xor_sync(0xffffffffu, rm, off));
            float mnew = fmaxf(m[a], rm);
            fac[a] = __expf(m[a] - mnew);
            m[a] = mnew;
            float rs = 0.f;
            #pragma unroll
            for (int c = 0; c < 4; c++) {
                float pv = __expf(s[a][c] - mnew);
                s[a][c] = pv;
                rs += pv;
            }
            #pragma unroll
            for (int off = 1; off < 16; off <<= 1)
                rs += __shfl_xor_sync(0xffffffffu, rs, off);
            l[a] = l[a] * fac[a] + rs;
        }
        #pragma unroll
        for (int a = 0; a < 4; a++)
            #pragma unroll
            for (int c = 0; c < 4; c++) o[a][c] *= fac[a];

        __syncthreads();
        #pragma unroll
        for (int c = 0; c < 4; c++) {
            float4 pv = make_float4(s[0][c], s[1][c], s[2][c], s[3][c]);
            *(float4*)&sKP[(tx * 4 + c) * 64 + ty * 4] = pv;
        }
        __syncthreads();

        #pragma unroll 16
        for (int jj = 0; jj < 64; jj++) {
            float4 pa = *(const float4*)&sKP[jj * 64 + ty * 4];
            float4 vb = *(const float4*)&sV[jj * 64 + tx * 4];
            o[0][0] = fmaf(pa.x, vb.x, o[0][0]); o[0][1] = fmaf(pa.x, vb.y, o[0][1]);
            o[0][2] = fmaf(pa.x, vb.z, o[0][2]); o[0][3] = fmaf(pa.x, vb.w, o[0][3]);
            o[1][0] = fmaf(pa.y, vb.x, o[1][0]); o[1][1] = fmaf(pa.y, vb.y, o[1][1]);
            o[1][2] = fmaf(pa.y, vb.z, o[1][2]); o[1][3] = fmaf(pa.y, vb.w, o[1][3]);
            o[2][0] = fmaf(pa.z, vb.x, o[2][0]); o[2][1] = fmaf(pa.z, vb.y, o[2][1]);
            o[2][2] = fmaf(pa.z, vb.z, o[2][2]); o[2][3] = fmaf(pa.z, vb.w, o[2][3]);
            o[3][0] = fmaf(pa.w, vb.x, o[3][0]); o[3][1] = fmaf(pa.w, vb.y, o[3][1]);
            o[3][2] = fmaf(pa.w, vb.z, o[3][2]); o[3][3] = fmaf(pa.w, vb.w, o[3][3]);
        }
    }

    #pragma unroll
    for (int a = 0; a < 4; a++) {
        float inv = 1.f / l[a];
        int qrow = q0 + ty * 4 + a;
        float4 v = make_float4(o[a][0] * inv, o[a][1] * inv,
                               o[a][2] * inv, o[a][3] * inv);
        *(float4*)&out[((size_t)(b * SEQ + qrow)) * CH + h * HDIM + tx * 4] = v;
    }
}

// ---------------- launcher ---------------------------------------------------
extern "C" void kernel_launch(void* const* d_in, const int* in_sizes, int n_in,
                              void* d_out, int out_size)
{
    const float* x     = (const float*)d_in[0];
    const float* A_log = (const float*)d_in[1];
    const float* Wd    = (const float*)d_in[2];
    const float* bd    = (const float*)d_in[3];
    const float* WB    = (const float*)d_in[4];
    const float* WC    = (const float*)d_in[5];
    const float* Wq    = (const float*)d_in[6];
    const float* bq    = (const float*)d_in[7];
    const float* Wk    = (const float*)d_in[8];
    const float* bk    = (const float*)d_in[9];
    const float* Wv    = (const float*)d_in[10];
    const float* bv    = (const float*)d_in[11];
    const float* Wx    = (const float*)d_in[12];
    const float* bx    = (const float*)d_in[13];
    const float* Wo    = (const float*)d_in[14];
    const float* bo    = (const float*)d_in[15];
    const float* ln_g  = (const float*)d_in[16];
    const float* ln_b  = (const float*)d_in[17];
    const float* temp  = (const float*)d_in[18];
    float* out = (float*)d_out;

    float* xb = nullptr; cudaGetSymbolAddress((void**)&xb, g_xb);
    float* dl = nullptr; cudaGetSymbolAddress((void**)&dl, g_dl);
    float* Bm = nullptr; cudaGetSymbolAddress((void**)&Bm, g_Bm);
    float* Cm = nullptr; cudaGetSymbolAddress((void**)&Cm, g_Cm);
    float* yb = nullptr; cudaGetSymbolAddress((void**)&yb, g_y);
    float* hy = nullptr; cudaGetSymbolAddress((void**)&hy, g_hy);
    float* Qb = nullptr; cudaGetSymbolAddress((void**)&Qb, g_Q);
    float* Kb = nullptr; cudaGetSymbolAddress((void**)&Kb, g_K);
    float* Vb = nullptr; cudaGetSymbolAddress((void**)&Vb, g_V);
    float* at = nullptr; cudaGetSymbolAddress((void**)&at, g_at);
    float* hloc = nullptr; cudaGetSymbolAddress((void**)&hloc, g_hloc);
    float* hin  = nullptr; cudaGetSymbolAddress((void**)&hin,  g_hin);
    float* dsum = nullptr; cudaGetSymbolAddress((void**)&dsum, g_dsum);
    __nv_bfloat16* ahi = nullptr; cudaGetSymbolAddress((void**)&ahi, g_ahi);
    __nv_bfloat16* alo = nullptr; cudaGetSymbolAddress((void**)&alo, g_alo);
    __nv_bfloat16* wt  = nullptr; cudaGetSymbolAddress((void**)&wt,  g_wt);

    cudaFuncSetAttribute(mm_bf16, cudaFuncAttributeMaxDynamicSharedMemorySize,
                         MM_SMEM);

    const size_t WSZ = (size_t)CH * CH;
    dim3 tgrid(32, 32), tblk(32, 8);
    cvt_wt<<<tgrid, tblk>>>(Wx, wt + 0*WSZ,  wt + 1*WSZ);
    cvt_wt<<<tgrid, tblk>>>(Wd, wt + 2*WSZ,  wt + 3*WSZ);
    cvt_wt<<<tgrid, tblk>>>(Wq, wt + 4*WSZ,  wt + 5*WSZ);
    cvt_wt<<<tgrid, tblk>>>(Wk, wt + 6*WSZ,  wt + 7*WSZ);
    cvt_wt<<<tgrid, tblk>>>(Wv, wt + 8*WSZ,  wt + 9*WSZ);
    cvt_wt<<<tgrid, tblk>>>(Wo, wt + 10*WSZ, wt + 11*WSZ);

    dim3 mmg(CH / 128, NTOK / 128);   // (8, 32)

    cvt_act<<<NTOK * CH / 1024, 256>>>(x, ahi, alo);
    mm_bf16<<<mmg, 256, MM_SMEM>>>(ahi, alo, wt + 0*WSZ, wt + 1*WSZ, bx, xb, 0);
    mm_bf16<<<mmg, 256, MM_SMEM>>>(ahi, alo, wt + 2*WSZ, wt + 3*WSZ, bd, dl, 1);
    bc_k<<<NTOK / 8, 256>>>(x, WB, WC, Bm, Cm);

    dim3 scan_grid(CH / 64, NCH, BATCH);
    scan1_k<<<scan_grid, 64>>>(xb, dl, Bm, A_log, hloc, dsum);
    scan2_k<<<BATCH * CH / 128, 128>>>(hloc, dsum, A_log, hin);
    scan3_k<<<scan_grid, 64>>>(xb, dl, Bm, Cm, A_log, hin, yb);

    ln_k<<<NTOK, 256>>>(xb, yb, ln_g, ln_b, hy);

    cvt_act<<<NTOK * CH / 1024, 256>>>(hy, ahi, alo);
    mm_bf16<<<mmg, 256, MM_SMEM>>>(ahi, alo, wt + 4*WSZ, wt + 5*WSZ, bq, Qb, 2);
    mm_bf16<<<mmg, 256, MM_SMEM>>>(ahi, alo, wt + 6*WSZ, wt + 7*WSZ, bk, Kb, 2);
    mm_bf16<<<mmg, 256, MM_SMEM>>>(ahi, alo, wt + 8*WSZ, wt + 9*WSZ, bv, Vb, 2);

    flash_k<<<dim3(SEQ / 64, BATCH * NH), 256>>>(Qb, Kb, Vb, temp, at);

    cvt_act<<<NTOK * CH / 1024, 256>>>(at, ahi, alo);
    mm_bf16<<<mmg, 256, MM_SMEM>>>(ahi, alo, wt + 10*WSZ, wt + 11*WSZ, bo, out, 0);
}

// round 6
// speedup vs baseline: 2.8711x; 1.6684x over previous
#include <cuda_runtime.h>
#include <cuda_bf16.h>
#include <cstdint>
#include <cmath>

#define BATCH 2
#define SEQ   2048
#define CH    1024
#define NH    16
#define SST   16
#define HDIM  64
#define NTOK  (BATCH*SEQ)   // 4096

#define NCH   32            // time chunks for parallel scan
#define CLEN  (SEQ/NCH)     // 64 steps per chunk
#define SGRP  16            // staging group (steps)

// ---------------- device scratch (allocation-free) --------------------------
__device__ float g_xb[(size_t)NTOK*CH];
__device__ float g_dl[(size_t)NTOK*CH];
__device__ float g_Bm[(size_t)NTOK*SST];
__device__ float g_Cm[(size_t)NTOK*SST];
__device__ float g_y [(size_t)NTOK*CH];
__device__ float g_hy[(size_t)NTOK*CH];
__device__ float g_at[(size_t)NTOK*CH];   // attention out, (B,T,C)
// parallel-scan intermediates
__device__ float g_hloc[(size_t)BATCH*NCH*CH*SST];
__device__ float g_hin [(size_t)BATCH*NCH*CH*SST];
__device__ float g_dsum[(size_t)BATCH*NCH*CH];
// bf16 split activations + transposed split weights
__device__ __nv_bfloat16 g_ahi[(size_t)NTOK*CH];
__device__ __nv_bfloat16 g_alo[(size_t)NTOK*CH];
__device__ __nv_bfloat16 g_wt [(size_t)12*CH*CH];  // 6 weights x {hi,lo}, [N][K]
// bf16 split QKV in (B,H,T,HD) layout
__device__ __nv_bfloat16 g_Qh[(size_t)NTOK*CH];
__device__ __nv_bfloat16 g_Ql[(size_t)NTOK*CH];
__device__ __nv_bfloat16 g_Kh[(size_t)NTOK*CH];
__device__ __nv_bfloat16 g_Kl[(size_t)NTOK*CH];
__device__ __nv_bfloat16 g_Vh[(size_t)NTOK*CH];
__device__ __nv_bfloat16 g_Vl[(size_t)NTOK*CH];

__device__ __forceinline__ float softplus_f(float x) {
    return (x > 20.f) ? x : log1pf(expf(x));
}

__device__ __forceinline__ uint32_t s2u(const void* p) {
    uint32_t a;
    asm("{ .reg .u64 t; cvta.to.shared.u64 t, %1; cvt.u32.u64 %0, t; }"
        : "=r"(a) : "l"(p));
    return a;
}

#define CP_ASYNC16(saddr, gptr) \
    asm volatile("cp.async.cg.shared.global [%0], [%1], 16;" \
                 :: "r"(saddr), "l"(gptr))
#define CP_COMMIT()  asm volatile("cp.async.commit_group;")
#define CP_WAIT1()   asm volatile("cp.async.wait_group 1;")
#define CP_WAIT0()   asm volatile("cp.async.wait_group 0;")

#define LDSM4(R0, R1, R2, R3, addr) \
    asm volatile("ldmatrix.sync.aligned.m8n8.x4.shared.b16 {%0,%1,%2,%3}, [%4];" \
                 : "=r"(R0), "=r"(R1), "=r"(R2), "=r"(R3) : "r"(addr))
#define LDSM4T(R0, R1, R2, R3, addr) \
    asm volatile("ldmatrix.sync.aligned.m8n8.x4.trans.shared.b16 {%0,%1,%2,%3}, [%4];" \
                 : "=r"(R0), "=r"(R1), "=r"(R2), "=r"(R3) : "r"(addr))

#define MMA16816(C, A0, A1, A2, A3, B0, B1) \
    asm volatile("mma.sync.aligned.m16n8k16.row.col.f32.bf16.bf16.f32 " \
                 "{%0,%1,%2,%3}, {%4,%5,%6,%7}, {%8,%9}, {%0,%1,%2,%3};" \
                 : "+f"((C)[0]), "+f"((C)[1]), "+f"((C)[2]), "+f"((C)[3]) \
                 : "r"(A0), "r"(A1), "r"(A2), "r"(A3), "r"(B0), "r"(B1))

// ============================================================================
// bf16-split tensor-core GEMM: out[4096,1024] = A @ W^T (+bias)
// flags bit0: softplus epilogue.  bit1: fp32 (B,H,T,HD) head layout.
// flags bit2: bf16 hi/lo split output in (B,H,T,HD) head layout.
// ============================================================================
#define TPAD   40
#define TROWB  (TPAD*2)
#define TILE_B (128*TROWB)
#define STG_B  (4*TILE_B)
#define MM_SMEM (2*STG_B)

__global__ __launch_bounds__(256, 2)
void mm_bf16(const __nv_bfloat16* __restrict__ Ahi,
             const __nv_bfloat16* __restrict__ Alo,
             const __nv_bfloat16* __restrict__ Bhi,
             const __nv_bfloat16* __restrict__ Blo,
             const float* __restrict__ bias, float* __restrict__ out,
             __nv_bfloat16* __restrict__ outH, __nv_bfloat16* __restrict__ outL,
             int flags)
{
    extern __shared__ char smem[];
    const int tid  = threadIdx.x;
    const int wid  = tid >> 5, lane = tid & 31;
    const int m0 = blockIdx.y << 7, n0 = blockIdx.x << 7;
    const int wm = wid & 1, wn = wid >> 1;
    const uint32_t sbase = s2u(smem);

    const int r0s = tid >> 2,         sg0 = tid & 3;
    const int r1s = r0s + 64,         sg1 = sg0;
    const uint32_t d0 = r0s * TROWB + sg0 * 16;
    const uint32_t d1 = r1s * TROWB + sg1 * 16;

    const __nv_bfloat16* tp[4] = {Ahi, Alo, Bhi, Blo};

    float acc[4][4][4];
    #pragma unroll
    for (int i = 0; i < 4; i++)
        #pragma unroll
        for (int j = 0; j < 4; j++)
            #pragma unroll
            for (int q = 0; q < 4; q++) acc[i][j][q] = 0.f;

    const uint32_t aoff = (uint32_t)(wm * 64 + (lane & 15)) * TROWB
                        + ((lane >> 4) & 1) * 16;
    const uint32_t boff = (uint32_t)(wn * 32 + ((lane >> 4) & 1) * 8 + (lane & 7)) * TROWB
                        + ((lane >> 3) & 1) * 16;

    {
        const int k0 = 0;
        const uint32_t sb = sbase;
        #pragma unroll
        for (int t = 0; t < 4; t++) {
            const int rb = (t < 2) ? m0 : n0;
            const __nv_bfloat16* g = tp[t];
            CP_ASYNC16(sb + t * TILE_B + d0,
                       g + (size_t)(rb + r0s) * CH + k0 + sg0 * 8);
            CP_ASYNC16(sb + t * TILE_B + d1,
                       g + (size_t)(rb + r1s) * CH + k0 + sg1 * 8);
        }
        CP_COMMIT();
    }

    const int NC = CH / 32;
    for (int ck = 0; ck < NC; ck++) {
        if (ck + 1 < NC) {
            const int k0 = (ck + 1) << 5;
            const uint32_t sb = sbase + ((ck + 1) & 1) * STG_B;
            #pragma unroll
            for (int t = 0; t < 4; t++) {
                const int rb = (t < 2) ? m0 : n0;
                const __nv_bfloat16* g = tp[t];
                CP_ASYNC16(sb + t * TILE_B + d0,
                           g + (size_t)(rb + r0s) * CH + k0 + sg0 * 8);
                CP_ASYNC16(sb + t * TILE_B + d1,
                           g + (size_t)(rb + r1s) * CH + k0 + sg1 * 8);
            }
            CP_COMMIT();
            CP_WAIT1();
        } else {
            CP_WAIT0();
        }
        __syncthreads();

        const uint32_t sb = sbase + (ck & 1) * STG_B;
        #pragma unroll
        for (int ks = 0; ks < 2; ks++) {
            const uint32_t ka  = sb + aoff + ks * 32;
            const uint32_t ka2 = ka + TILE_B;
            const uint32_t kb  = sb + 2 * TILE_B + boff + ks * 32;
            const uint32_t kb2 = kb + TILE_B;

            uint32_t a[4][4], bh[2][4], bl[2][4];
            #pragma unroll
            for (int i = 0; i < 4; i++)
                LDSM4(a[i][0], a[i][1], a[i][2], a[i][3], ka + i * 16 * TROWB);
            #pragma unroll
            for (int j = 0; j < 2; j++)
                LDSM4(bh[j][0], bh[j][1], bh[j][2], bh[j][3], kb + j * 16 * TROWB);
            #pragma unroll
            for (int i = 0; i < 4; i++)
                #pragma unroll
                for (int jj = 0; jj < 4; jj++)
                    MMA16816(acc[i][jj], a[i][0], a[i][1], a[i][2], a[i][3],
                             bh[jj >> 1][(jj & 1) * 2], bh[jj >> 1][(jj & 1) * 2 + 1]);
            #pragma unroll
            for (int j = 0; j < 2; j++)
                LDSM4(bl[j][0], bl[j][1], bl[j][2], bl[j][3], kb2 + j * 16 * TROWB);
            #pragma unroll
            for (int i = 0; i < 4; i++)
                #pragma unroll
                for (int jj = 0; jj < 4; jj++)
                    MMA16816(acc[i][jj], a[i][0], a[i][1], a[i][2], a[i][3],
                             bl[jj >> 1][(jj & 1) * 2], bl[jj >> 1][(jj & 1) * 2 + 1]);
            #pragma unroll
            for (int i = 0; i < 4; i++)
                LDSM4(a[i][0], a[i][1], a[i][2], a[i][3], ka2 + i * 16 * TROWB);
            #pragma unroll
            for (int i = 0; i < 4; i++)
                #pragma unroll
                for (int jj = 0; jj < 4; jj++)
                    MMA16816(acc[i][jj], a[i][0], a[i][1], a[i][2], a[i][3],
                             bh[jj >> 1][(jj & 1) * 2], bh[jj >> 1][(jj & 1) * 2 + 1]);
        }
        __syncthreads();
    }

    #pragma unroll
    for (int i = 0; i < 4; i++) {
        #pragma unroll
        for (int jj = 0; jj < 4; jj++) {
            const int row = m0 + wm * 64 + i * 16 + (lane >> 2);
            const int col = n0 + wn * 32 + jj * 8 + (lane & 3) * 2;
            float b0 = bias[col], b1 = bias[col + 1];
            float v0 = acc[i][jj][0] + b0, v1 = acc[i][jj][1] + b1;
            float v2 = acc[i][jj][2] + b0, v3 = acc[i][jj][3] + b1;
            if (flags & 1) {
                v0 = softplus_f(v0); v1 = softplus_f(v1);
                v2 = softplus_f(v2); v3 = softplus_f(v3);
            }
            if (flags & 4) {
                const int hh = col >> 6, hd = col & (HDIM - 1);
                const int bb0 = row >> 11, t0 = row & (SEQ - 1);
                size_t base0 = ((((size_t)bb0 * NH + hh) * SEQ) + t0) * HDIM + hd;
                const int r8 = row + 8;
                const int bb1 = r8 >> 11, t1 = r8 & (SEQ - 1);
                size_t base1 = ((((size_t)bb1 * NH + hh) * SEQ) + t1) * HDIM + hd;
                __nv_bfloat16 h0 = __float2bfloat16(v0);
                __nv_bfloat16 h1 = __float2bfloat16(v1);
                __nv_bfloat16 h2 = __float2bfloat16(v2);
                __nv_bfloat16 h3 = __float2bfloat16(v3);
                *(__nv_bfloat162*)(outH + base0) = __nv_bfloat162(h0, h1);
                *(__nv_bfloat162*)(outH + base1) = __nv_bfloat162(h2, h3);
                *(__nv_bfloat162*)(outL + base0) = __nv_bfloat162(
                    __float2bfloat16(v0 - __bfloat162float(h0)),
                    __float2bfloat16(v1 - __bfloat162float(h1)));
                *(__nv_bfloat162*)(outL + base1) = __nv_bfloat162(
                    __float2bfloat16(v2 - __bfloat162float(h2)),
                    __float2bfloat16(v3 - __bfloat162float(h3)));
            } else if (flags & 2) {
                const int hh = col >> 6, hd = col & (HDIM - 1);
                const int bb0 = row >> 11, t0 = row & (SEQ - 1);
                size_t base0 = ((((size_t)bb0 * NH + hh) * SEQ) + t0) * HDIM + hd;
                *(float2*)(out + base0) = make_float2(v0, v1);
                const int r8 = row + 8;
                const int bb1 = r8 >> 11, t1 = r8 & (SEQ - 1);
                size_t base1 = ((((size_t)bb1 * NH + hh) * SEQ) + t1) * HDIM + hd;
                *(float2*)(out + base1) = make_float2(v2, v3);
            } else {
                *(float2*)(out + (size_t)row * CH + col)       = make_float2(v0, v1);
                *(float2*)(out + (size_t)(row + 8) * CH + col) = make_float2(v2, v3);
            }
        }
    }
}

// ---------------- fp32 -> bf16 hi/lo split (activations) --------------------
__global__ __launch_bounds__(256)
void cvt_act(const float* __restrict__ in, __nv_bfloat16* __restrict__ hi,
             __nv_bfloat16* __restrict__ lo)
{
    size_t i = ((size_t)blockIdx.x * 256 + threadIdx.x) * 4;
    float4 v = *(const float4*)(in + i);
    __nv_bfloat16 h0 = __float2bfloat16(v.x);
    __nv_bfloat16 h1 = __float2bfloat16(v.y);
    __nv_bfloat16 h2 = __float2bfloat16(v.z);
    __nv_bfloat16 h3 = __float2bfloat16(v.w);
    __nv_bfloat16 l0 = __float2bfloat16(v.x - __bfloat162float(h0));
    __nv_bfloat16 l1 = __float2bfloat16(v.y - __bfloat162float(h1));
    __nv_bfloat16 l2 = __float2bfloat16(v.z - __bfloat162float(h2));
    __nv_bfloat16 l3 = __float2bfloat16(v.w - __bfloat162float(h3));
    __nv_bfloat162* h2p = (__nv_bfloat162*)(hi + i);
    __nv_bfloat162* l2p = (__nv_bfloat162*)(lo + i);
    h2p[0] = __nv_bfloat162(h0, h1); h2p[1] = __nv_bfloat162(h2, h3);
    l2p[0] = __nv_bfloat162(l0, l1); l2p[1] = __nv_bfloat162(l2, l3);
}

// ---------------- weight transpose + hi/lo split: W[K][N] -> T[N][K] --------
__global__ __launch_bounds__(256)
void cvt_wt(const float* __restrict__ W, __nv_bfloat16* __restrict__ Th,
            __nv_bfloat16* __restrict__ Tl)
{
    __shared__ float t[32][33];
    int tx = threadIdx.x, ty = threadIdx.y;
    int nb = blockIdx.x * 32, kb = blockIdx.y * 32;
    #pragma unroll
    for (int j = 0; j < 32; j += 8)
        t[ty + j][tx] = W[(size_t)(kb + ty + j) * CH + nb + tx];
    __syncthreads();
    #pragma unroll
    for (int j = 0; j < 32; j += 8) {
        float v = t[tx][ty + j];
        __nv_bfloat16 h = __float2bfloat16(v);
        __nv_bfloat16 l = __float2bfloat16(v - __bfloat162float(h));
        size_t o = (size_t)(nb + ty + j) * CH + kb + tx;
        Th[o] = h; Tl[o] = l;
    }
}

// ---------------- small B/C projection ---------------------------------------
__global__ __launch_bounds__(256)
void bc_k(const float* __restrict__ x, const float* __restrict__ WB,
          const float* __restrict__ WC, float* __restrict__ Bm,
          float* __restrict__ Cm)
{
    __shared__ float xs[8][64];
    __shared__ float Ws[64][32];
    const int tid = threadIdx.x;
    const int tx = tid & 31, ty = tid >> 5;
    const int tok0 = blockIdx.x * 8;
    float acc = 0.f;

    for (int k0 = 0; k0 < CH; k0 += 64) {
        __syncthreads();
        if (tid < 128) {
            int t = tid >> 4, c4 = (tid & 15) * 4;
            *(float4*)&xs[t][c4] =
                *(const float4*)&x[(size_t)(tok0 + t) * CH + k0 + c4];
        }
        {
            int r = tid >> 2, c = (tid & 3) * 4;
            *(float4*)&Ws[r][c]      = *(const float4*)&WB[(size_t)(k0 + r) * SST + c];
            *(float4*)&Ws[r][16 + c] = *(const float4*)&WC[(size_t)(k0 + r) * SST + c];
        }
        __syncthreads();
        #pragma unroll
        for (int k = 0; k < 64; k++)
            acc = fmaf(xs[ty][k], Ws[k][tx], acc);
    }
    int tok = tok0 + ty;
    if (tx < 16) Bm[(size_t)tok * SST + tx] = acc;
    else         Cm[(size_t)tok * SST + (tx - 16)] = acc;
}

// ---------------- parallel scan, phase 1 -------------------------------------
__global__ __launch_bounds__(64)
void scan1_k(const float* __restrict__ xb, const float* __restrict__ dl,
             const float* __restrict__ Bm, const float* __restrict__ A_log,
             float* __restrict__ hloc, float* __restrict__ dsum)
{
    __shared__ float sB[SGRP * SST];
    const int tid = threadIdx.x;
    const int b = blockIdx.z, ck = blockIdx.y;
    const int c = blockIdx.x * 64 + tid;
    const int t0 = ck * CLEN;

    float A[SST];
    #pragma unroll
    for (int s = 0; s < SST; s++) A[s] = -expf(A_log[(size_t)c * SST + s]);
    float h[SST];
    #pragma unroll
    for (int s = 0; s < SST; s++) h[s] = 0.f;
    float Ds = 0.f;

    for (int g = 0; g < CLEN; g += SGRP) {
        const int tg = t0 + g;
        float rd[SGRP], rx[SGRP];
        size_t base = ((size_t)(b * SEQ + tg)) * CH + c;
        #pragma unroll
        for (int i = 0; i < SGRP; i++) {
            rd[i] = dl[base + (size_t)i * CH];
            rx[i] = xb[base + (size_t)i * CH];
        }
        __syncthreads();
        {
            size_t bb = ((size_t)(b * SEQ + tg)) * SST;
            ((float4*)sB)[tid] = ((const float4*)(Bm + bb))[tid];
        }
        __syncthreads();
        #pragma unroll
        for (int i = 0; i < SGRP; i++) {
            float d = rd[i];
            float dx = d * rx[i];
            Ds += d;
            #pragma unroll
            for (int s = 0; s < SST; s++) {
                float bar = __expf(d * A[s]);
                h[s] = fmaf(bar, h[s], dx * sB[i * SST + s]);
            }
        }
    }
    size_t o = (((size_t)(b * NCH + ck)) * CH + c) * SST;
    #pragma unroll
    for (int s4 = 0; s4 < SST; s4 += 4)
        *(float4*)&hloc[o + s4] = make_float4(h[s4], h[s4+1], h[s4+2], h[s4+3]);
    dsum[((size_t)(b * NCH + ck)) * CH + c] = Ds;
}

// ---------------- parallel scan, phase 2 -------------------------------------
__global__ __launch_bounds__(128)
void scan2_k(const float* __restrict__ hloc, const float* __restrict__ dsum,
             const float* __restrict__ A_log, float* __restrict__ hin)
{
    const int lane = blockIdx.x * 128 + threadIdx.x;
    const int b = lane >> 10, c = lane & (CH - 1);

    float A[SST];
    #pragma unroll
    for (int s = 0; s < SST; s++) A[s] = -expf(A_log[(size_t)c * SST + s]);
    float h[SST];
    #pragma unroll
    for (int s = 0; s < SST; s++) h[s] = 0.f;

    for (int ck = 0; ck < NCH; ck++) {
        size_t o = (((size_t)(b * NCH + ck)) * CH + c) * SST;
        #pragma unroll
        for (int s4 = 0; s4 < SST; s4 += 4)
            *(float4*)&hin[o + s4] = make_float4(h[s4], h[s4+1], h[s4+2], h[s4+3]);
        float Ds = dsum[((size_t)(b * NCH + ck)) * CH + c];
        #pragma unroll
        for (int s4 = 0; s4 < SST; s4 += 4) {
            float4 hl = *(const float4*)&hloc[o + s4];
            h[s4+0] = fmaf(__expf(Ds * A[s4+0]), h[s4+0], hl.x);
            h[s4+1] = fmaf(__expf(Ds * A[s4+1]), h[s4+1], hl.y);
            h[s4+2] = fmaf(__expf(Ds * A[s4+2]), h[s4+2], hl.z);
            h[s4+3] = fmaf(__expf(Ds * A[s4+3]), h[s4+3], hl.w);
        }
    }
}

// ---------------- parallel scan, phase 3 -------------------------------------
__global__ __launch_bounds__(64)
void scan3_k(const float* __restrict__ xb, const float* __restrict__ dl,
             const float* __restrict__ Bm, const float* __restrict__ Cm,
             const float* __restrict__ A_log, const float* __restrict__ hin,
             float* __restrict__ y)
{
    __shared__ float sB[SGRP * SST];
    __shared__ float sC[SGRP * SST];
    const int tid = threadIdx.x;
    const int b = blockIdx.z, ck = blockIdx.y;
    const int c = blockIdx.x * 64 + tid;
    const int t0 = ck * CLEN;

    float A[SST];
    #pragma unroll
    for (int s = 0; s < SST; s++) A[s] = -expf(A_log[(size_t)c * SST + s]);
    float h[SST];
    {
        size_t o = (((size_t)(b * NCH + ck)) * CH + c) * SST;
        #pragma unroll
        for (int s4 = 0; s4 < SST; s4 += 4) {
            float4 v = *(const float4*)&hin[o + s4];
            h[s4] = v.x; h[s4+1] = v.y; h[s4+2] = v.z; h[s4+3] = v.w;
        }
    }

    for (int g = 0; g < CLEN; g += SGRP) {
        const int tg = t0 + g;
        float rd[SGRP], rx[SGRP];
        size_t base = ((size_t)(b * SEQ + tg)) * CH + c;
        #pragma unroll
        for (int i = 0; i < SGRP; i++) {
            rd[i] = dl[base + (size_t)i * CH];
            rx[i] = xb[base + (size_t)i * CH];
        }
        __syncthreads();
        {
            size_t bb = ((size_t)(b * SEQ + tg)) * SST;
            ((float4*)sB)[tid] = ((const float4*)(Bm + bb))[tid];
            ((float4*)sC)[tid] = ((const float4*)(Cm + bb))[tid];
        }
        __syncthreads();
        #pragma unroll
        for (int i = 0; i < SGRP; i++) {
            float d = rd[i];
            float dx = d * rx[i];
            float yv = 0.f;
            #pragma unroll
            for (int s = 0; s < SST; s++) {
                float bar = __expf(d * A[s]);
                float hh = fmaf(bar, h[s], dx * sB[i * SST + s]);
                h[s] = hh;
                yv = fmaf(hh, sC[i * SST + s], yv);
            }
            y[base + (size_t)i * CH] = yv;
        }
    }
}

// ---------------- LayerNorm(x_base + y) -------------------------------------
__global__ __launch_bounds__(256)
void ln_k(const float* __restrict__ xb, const float* __restrict__ y,
          const float* __restrict__ gam, const float* __restrict__ bet,
          float* __restrict__ out)
{
    const int tok = blockIdx.x, tid = threadIdx.x;
    const float4* a4 = (const float4*)(xb + (size_t)tok * CH);
    const float4* b4 = (const float4*)(y  + (size_t)tok * CH);
    float4 v = a4[tid], w = b4[tid];
    v.x += w.x; v.y += w.y; v.z += w.z; v.w += w.w;
    float sum = v.x + v.y + v.z + v.w;
    float sq  = v.x * v.x + v.y * v.y + v.z * v.z + v.w * v.w;
    #pragma unroll
    for (int off = 16; off; off >>= 1) {
        sum += __shfl_xor_sync(0xffffffffu, sum, off);
        sq  += __shfl_xor_sync(0xffffffffu, sq,  off);
    }
    __shared__ float s1[8], s2[8];
    __shared__ float mu_s, rstd_s;
    if ((tid & 31) == 0) { s1[tid >> 5] = sum; s2[tid >> 5] = sq; }
    __syncthreads();
    if (tid == 0) {
        float t1 = 0.f, t2 = 0.f;
        #pragma unroll
        for (int i = 0; i < 8; i++) { t1 += s1[i]; t2 += s2[i]; }
        float mu = t1 * (1.f / CH);
        float var = t2 * (1.f / CH) - mu * mu;
        mu_s = mu;
        rstd_s = rsqrtf(var + 1e-5f);
    }
    __syncthreads();
    float mu = mu_s, rstd = rstd_s;
    float4 g = ((const float4*)gam)[tid];
    float4 be = ((const float4*)bet)[tid];
    float4 o;
    o.x = (v.x - mu) * rstd * g.x + be.x;
    o.y = (v.y - mu) * rstd * g.y + be.y;
    o.z = (v.z - mu) * rstd * g.z + be.z;
    o.w = (v.w - mu) * rstd * g.w + be.w;
    ((float4*)(out + (size_t)tok * CH))[tid] = o;
}

// ============================================================================
// Tensor-core causal flash attention (bf16 split, fp32 softmax/accum)
// 128 threads (4 warps), q-tile 64 (16 rows/warp), k-blocks of 64.
// ============================================================================
#define FRS   144                       // padded row bytes (64 bf16 + 8 pad)
#define FTILE (64*FRS)                  // 9216 per tile
#define FSTG  (4*FTILE)                 // Kh, Kl, Vh, Vl
#define F_SMEM (2*FTILE + 2*FSTG)       // Qh, Ql + 2 stages = 92160

__global__ __launch_bounds__(128)
void flash_mma(const __nv_bfloat16* __restrict__ Qh,
               const __nv_bfloat16* __restrict__ Ql,
               const __nv_bfloat16* __restrict__ Kh,
               const __nv_bfloat16* __restrict__ Kl,
               const __nv_bfloat16* __restrict__ Vh,
               const __nv_bfloat16* __restrict__ Vl,
               const float* __restrict__ temp, float* __restrict__ out)
{
    extern __shared__ char smem[];
    const int tid = threadIdx.x;
    const int wid = tid >> 5, lane = tid & 31;
    const int qt = (int)gridDim.x - 1 - (int)blockIdx.x;  // reversed schedule
    const int bh = blockIdx.y;
    const int b = bh >> 4, h = bh & 15;
    const int q0 = qt << 6;
    const uint32_t sb = s2u(smem);
    const uint32_t sQ = sb;                 // Qh at 0, Ql at FTILE
    const uint32_t sS0 = sb + 2 * FTILE;    // stages

    const float sc = softplus_f(temp[h]) * 0.125f;

    const __nv_bfloat16* Qhg = Qh + (size_t)bh * SEQ * HDIM + (size_t)q0 * HDIM;
    const __nv_bfloat16* Qlg = Ql + (size_t)bh * SEQ * HDIM + (size_t)q0 * HDIM;
    const __nv_bfloat16* kvg[4] = {
        Kh + (size_t)bh * SEQ * HDIM, Kl + (size_t)bh * SEQ * HDIM,
        Vh + (size_t)bh * SEQ * HDIM, Vl + (size_t)bh * SEQ * HDIM };

    // ---- cp.async prologue: Q (hi+lo) + stage 0
    #pragma unroll
    for (int i = 0; i < 8; i++) {
        int slot = tid + i * 128;           // 1024 slots: 512 hi + 512 lo
        int buf = slot >> 9, idx = slot & 511;
        int row = idx >> 3, ch = idx & 7;
        const __nv_bfloat16* src = (buf ? Qlg : Qhg) + row * HDIM + ch * 8;
        CP_ASYNC16(sQ + buf * FTILE + row * FRS + ch * 16, src);
    }
    {
        #pragma unroll
        for (int i = 0; i < 16; i++) {
            int slot = tid + i * 128;       // 2048 slots
            int buf = slot >> 9, idx = slot & 511;
            int row = idx >> 3, ch = idx & 7;
            CP_ASYNC16(sS0 + buf * FTILE + row * FRS + ch * 16,
                       kvg[buf] + row * HDIM + ch * 8);
        }
        CP_COMMIT();
    }
    if (qt >= 1) {
        #pragma unroll
        for (int i = 0; i < 16; i++) {
            int slot = tid + i * 128;
            int buf = slot >> 9, idx = slot & 511;
            int row = idx >> 3, ch = idx & 7;
            CP_ASYNC16(sS0 + FSTG + buf * FTILE + row * FRS + ch * 16,
                       kvg[buf] + (64 + row) * HDIM + ch * 8);
        }
        CP_COMMIT();
    }

    // ldsm offsets
    const uint32_t aoff = (uint32_t)(wid * 16 + (lane & 15)) * FRS
                        + ((lane >> 4) & 1) * 16;
    const uint32_t kboff = (uint32_t)(((lane >> 4) & 1) * 8 + (lane & 7)) * FRS
                         + ((lane >> 3) & 1) * 16;
    const uint32_t vtoff = (uint32_t)((lane & 7) + ((lane >> 3) & 1) * 8) * FRS
                         + ((lane >> 4) & 1) * 16;

    uint32_t qh[4][4], ql[4][4];
    float O[8][4];
    #pragma unroll
    for (int j = 0; j < 8; j++)
        #pragma unroll
        for (int q = 0; q < 4; q++) O[j][q] = 0.f;
    float m0v = -1e30f, m1v = -1e30f, l0v = 0.f, l1v = 0.f;

    const int r_in_w = lane >> 2;              // 0..7
    const int row0g = q0 + wid * 16 + r_in_w;  // global q row (half 0)
    const int cql = (lane & 3) * 2;            // col within n8 tile

    for (int kb = 0; kb <= qt; kb++) {
        if (kb < qt) CP_WAIT1(); else CP_WAIT0();
        __syncthreads();

        if (kb == 0) {
            #pragma unroll
            for (int ks = 0; ks < 4; ks++) {
                LDSM4(qh[ks][0], qh[ks][1], qh[ks][2], qh[ks][3],
                      sQ + aoff + ks * 32);
                LDSM4(ql[ks][0], ql[ks][1], ql[ks][2], ql[ks][3],
                      sQ + FTILE + aoff + ks * 32);
            }
        }

        const uint32_t st = sS0 + (kb & 1) * FSTG;
        // ---- S = Q K^T (3-term)
        float S[8][4];
        #pragma unroll
        for (int j = 0; j < 8; j++)
            #pragma unroll
            for (int q = 0; q < 4; q++) S[j][q] = 0.f;

        #pragma unroll
        for (int ks = 0; ks < 4; ks++) {
            #pragma unroll
            for (int g = 0; g < 4; g++) {
                uint32_t bh0, bh1, bh2, bh3, bl0, bl1, bl2, bl3;
                uint32_t kaddr = st + kboff + g * 16 * FRS + ks * 32;
                LDSM4(bh0, bh1, bh2, bh3, kaddr);
                LDSM4(bl0, bl1, bl2, bl3, kaddr + FTILE);
                MMA16816(S[2*g],   qh[ks][0], qh[ks][1], qh[ks][2], qh[ks][3], bh0, bh1);
                MMA16816(S[2*g+1], qh[ks][0], qh[ks][1], qh[ks][2], qh[ks][3], bh2, bh3);
                MMA16816(S[2*g],   qh[ks][0], qh[ks][1], qh[ks][2], qh[ks][3], bl0, bl1);
                MMA16816(S[2*g+1], qh[ks][0], qh[ks][1], qh[ks][2], qh[ks][3], bl2, bl3);
                MMA16816(S[2*g],   ql[ks][0], ql[ks][1], ql[ks][2], ql[ks][3], bh0, bh1);
                MMA16816(S[2*g+1], ql[ks][0], ql[ks][1], ql[ks][2], ql[ks][3], bh2, bh3);
            }
        }

        // ---- scale + mask (diagonal block only)
        #pragma unroll
        for (int j = 0; j < 8; j++)
            #pragma unroll
            for (int q = 0; q < 4; q++) S[j][q] *= sc;
        if (kb == qt) {
            #pragma unroll
            for (int j = 0; j < 8; j++) {
                #pragma unroll
                for (int q = 0; q < 4; q++) {
                    int col = (kb << 6) + j * 8 + cql + (q & 1);
                    int row = row0g + (q >> 1) * 8;
                    if (col > row) S[j][q] = -1e30f;
                }
            }
        }

        // ---- online softmax (rows r_in_w and r_in_w+8)
        float mx0 = -1e30f, mx1 = -1e30f;
        #pragma unroll
        for (int j = 0; j < 8; j++) {
            mx0 = fmaxf(mx0, fmaxf(S[j][0], S[j][1]));
            mx1 = fmaxf(mx1, fmaxf(S[j][2], S[j][3]));
        }
        mx0 = fmaxf(mx0, __shfl_xor_sync(0xffffffffu, mx0, 1));
        mx0 = fmaxf(mx0, __shfl_xor_sync(0xffffffffu, mx0, 2));
        mx1 = fmaxf(mx1, __shfl_xor_sync(0xffffffffu, mx1, 1));
        mx1 = fmaxf(mx1, __shfl_xor_sync(0xffffffffu, mx1, 2));
        float mn0 = fmaxf(m0v, mx0), mn1 = fmaxf(m1v, mx1);
        float fac0 = __expf(m0v - mn0), fac1 = __expf(m1v - mn1);
        m0v = mn0; m1v = mn1;
        float rs0 = 0.f, rs1 = 0.f;
        #pragma unroll
        for (int j = 0; j < 8; j++) {
            S[j][0] = __expf(S[j][0] - mn0); rs0 += S[j][0];
            S[j][1] = __expf(S[j][1] - mn0); rs0 += S[j][1];
            S[j][2] = __expf(S[j][2] - mn1); rs1 += S[j][2];
            S[j][3] = __expf(S[j][3] - mn1); rs1 += S[j][3];
        }
        rs0 += __shfl_xor_sync(0xffffffffu, rs0, 1);
        rs0 += __shfl_xor_sync(0xffffffffu, rs0, 2);
        rs1 += __shfl_xor_sync(0xffffffffu, rs1, 1);
        rs1 += __shfl_xor_sync(0xffffffffu, rs1, 2);
        l0v = l0v * fac0 + rs0;
        l1v = l1v * fac1 + rs1;
        #pragma unroll
        for (int j = 0; j < 8; j++) {
            O[j][0] *= fac0; O[j][1] *= fac0;
            O[j][2] *= fac1; O[j][3] *= fac1;
        }

        // ---- O += P V (3-term), P frags built in-register
        #pragma unroll
        for (int ks = 0; ks < 4; ks++) {
            uint32_t ph[4], pl[4];
            #pragma unroll
            for (int half = 0; half < 2; half++) {   // ntile 2ks, 2ks+1
                int j = 2 * ks + half;
                float f0 = S[j][0], f1 = S[j][1], f2 = S[j][2], f3 = S[j][3];
                __nv_bfloat162 h01 = __floats2bfloat162_rn(f0, f1);
                __nv_bfloat162 h23 = __floats2bfloat162_rn(f2, f3);
                __nv_bfloat162 l01 = __floats2bfloat162_rn(
                    f0 - __bfloat162float(h01.x), f1 - __bfloat162float(h01.y));
                __nv_bfloat162 l23 = __floats2bfloat162_rn(
                    f2 - __bfloat162float(h23.x), f3 - __bfloat162float(h23.y));
                ph[half * 1 + 0 + (half ? 1 : 0)] = 0; // placeholder (overwritten below)
                // a0/a1 from half 0; a2/a3 from half 1
                if (half == 0) {
                    ph[0] = *(uint32_t*)&h01; ph[1] = *(uint32_t*)&h23;
                    pl[0] = *(uint32_t*)&l01; pl[1] = *(uint32_t*)&l23;
                } else {
                    ph[2] = *(uint32_t*)&h01; ph[3] = *(uint32_t*)&h23;
                    pl[2] = *(uint32_t*)&l01; pl[3] = *(uint32_t*)&l23;
                }
            }
            #pragma unroll
            for (int g = 0; g < 4; g++) {
                uint32_t vh0, vh1, vh2, vh3, vl0, vl1, vl2, vl3;
                uint32_t vaddr = st + 2 * FTILE + vtoff + ks * 16 * FRS + g * 32;
                LDSM4T(vh0, vh1, vh2, vh3, vaddr);
                LDSM4T(vl0, vl1, vl2, vl3, vaddr + FTILE);
                MMA16816(O[2*g],   ph[0], ph[1], ph[2], ph[3], vh0, vh1);
                MMA16816(O[2*g+1], ph[0], ph[1], ph[2], ph[3], vh2, vh3);
                MMA16816(O[2*g],   ph[0], ph[1], ph[2], ph[3], vl0, vl1);
                MMA16816(O[2*g+1], ph[0], ph[1], ph[2], ph[3], vl2, vl3);
                MMA16816(O[2*g],   pl[0], pl[1], pl[2], pl[3], vh0, vh1);
                MMA16816(O[2*g+1], pl[0], pl[1], pl[2], pl[3], vh2, vh3);
            }
        }
        __syncthreads();

        // ---- prefetch stage kb+2
        if (kb + 2 <= qt) {
            const uint32_t sd = sS0 + (kb & 1) * FSTG;
            const int kr = (kb + 2) << 6;
            #pragma unroll
            for (int i = 0; i < 16; i++) {
                int slot = tid + i * 128;
                int buf = slot >> 9, idx = slot & 511;
                int row = idx >> 3, ch = idx & 7;
                CP_ASYNC16(sd + buf * FTILE + row * FRS + ch * 16,
                           kvg[buf] + (size_t)(kr + row) * HDIM + ch * 8);
            }
            CP_COMMIT();
        }
    }

    // ---- epilogue: out (B,T,C)
    float inv0 = 1.f / l0v, inv1 = 1.f / l1v;
    const int row_a = row0g, row_b = row0g + 8;
    #pragma unroll
    for (int j = 0; j < 8; j++) {
        int col = h * HDIM + j * 8 + cql;
        *(float2*)(out + ((size_t)(b * SEQ + row_a)) * CH + col) =
            make_float2(O[j][0] * inv0, O[j][1] * inv0);
        *(float2*)(out + ((size_t)(b * SEQ + row_b)) * CH + col) =
            make_float2(O[j][2] * inv1, O[j][3] * inv1);
    }
}

// ---------------- launcher ---------------------------------------------------
extern "C" void kernel_launch(void* const* d_in, const int* in_sizes, int n_in,
                              void* d_out, int out_size)
{
    const float* x     = (const float*)d_in[0];
    const float* A_log = (const float*)d_in[1];
    const float* Wd    = (const float*)d_in[2];
    const float* bd    = (const float*)d_in[3];
    const float* WB    = (const float*)d_in[4];
    const float* WC    = (const float*)d_in[5];
    const float* Wq    = (const float*)d_in[6];
    const float* bq    = (const float*)d_in[7];
    const float* Wk    = (const float*)d_in[8];
    const float* bk    = (const float*)d_in[9];
    const float* Wv    = (const float*)d_in[10];
    const float* bv    = (const float*)d_in[11];
    const float* Wx    = (const float*)d_in[12];
    const float* bx    = (const float*)d_in[13];
    const float* Wo    = (const float*)d_in[14];
    const float* bo    = (const float*)d_in[15];
    const float* ln_g  = (const float*)d_in[16];
    const float* ln_b  = (const float*)d_in[17];
    const float* temp  = (const float*)d_in[18];
    float* out = (float*)d_out;

    float* xb = nullptr; cudaGetSymbolAddress((void**)&xb, g_xb);
    float* dl = nullptr; cudaGetSymbolAddress((void**)&dl, g_dl);
    float* Bm = nullptr; cudaGetSymbolAddress((void**)&Bm, g_Bm);
    float* Cm = nullptr; cudaGetSymbolAddress((void**)&Cm, g_Cm);
    float* yb = nullptr; cudaGetSymbolAddress((void**)&yb, g_y);
    float* hy = nullptr; cudaGetSymbolAddress((void**)&hy, g_hy);
    float* at = nullptr; cudaGetSymbolAddress((void**)&at, g_at);
    float* hloc = nullptr; cudaGetSymbolAddress((void**)&hloc, g_hloc);
    float* hin  = nullptr; cudaGetSymbolAddress((void**)&hin,  g_hin);
    float* dsum = nullptr; cudaGetSymbolAddress((void**)&dsum, g_dsum);
    __nv_bfloat16* ahi = nullptr; cudaGetSymbolAddress((void**)&ahi, g_ahi);
    __nv_bfloat16* alo = nullptr; cudaGetSymbolAddress((void**)&alo, g_alo);
    __nv_bfloat16* wt  = nullptr; cudaGetSymbolAddress((void**)&wt,  g_wt);
    __nv_bfloat16 *qh, *ql, *kh, *kl, *vh, *vl;
    cudaGetSymbolAddress((void**)&qh, g_Qh);
    cudaGetSymbolAddress((void**)&ql, g_Ql);
    cudaGetSymbolAddress((void**)&kh, g_Kh);
    cudaGetSymbolAddress((void**)&kl, g_Kl);
    cudaGetSymbolAddress((void**)&vh, g_Vh);
    cudaGetSymbolAddress((void**)&vl, g_Vl);

    cudaFuncSetAttribute(mm_bf16, cudaFuncAttributeMaxDynamicSharedMemorySize,
                         MM_SMEM);
    cudaFuncSetAttribute(flash_mma, cudaFuncAttributeMaxDynamicSharedMemorySize,
                         F_SMEM);

    const size_t WSZ = (size_t)CH * CH;
    dim3 tgrid(32, 32), tblk(32, 8);
    dim3 mmg(CH / 128, NTOK / 128);

    // launches 1-5, then mm_bf16 as launch #6 (ncu -s 5 captures it)
    cvt_wt<<<tgrid, tblk>>>(Wx, wt + 0*WSZ,  wt + 1*WSZ);
    cvt_wt<<<tgrid, tblk>>>(Wd, wt + 2*WSZ,  wt + 3*WSZ);
    cvt_wt<<<tgrid, tblk>>>(Wq, wt + 4*WSZ,  wt + 5*WSZ);
    cvt_wt<<<tgrid, tblk>>>(Wk, wt + 6*WSZ,  wt + 7*WSZ);
    cvt_act<<<NTOK * CH / 1024, 256>>>(x, ahi, alo);
    mm_bf16<<<mmg, 256, MM_SMEM>>>(ahi, alo, wt + 0*WSZ, wt + 1*WSZ, bx, xb,
                                   nullptr, nullptr, 0);
    mm_bf16<<<mmg, 256, MM_SMEM>>>(ahi, alo, wt + 2*WSZ, wt + 3*WSZ, bd, dl,
                                   nullptr, nullptr, 1);
    cvt_wt<<<tgrid, tblk>>>(Wv, wt + 8*WSZ,  wt + 9*WSZ);
    cvt_wt<<<tgrid, tblk>>>(Wo, wt + 10*WSZ, wt + 11*WSZ);
    bc_k<<<NTOK / 8, 256>>>(x, WB, WC, Bm, Cm);

    dim3 scan_grid(CH / 64, NCH, BATCH);
    scan1_k<<<scan_grid, 64>>>(xb, dl, Bm, A_log, hloc, dsum);
    scan2_k<<<BATCH * CH / 128, 128>>>(hloc, dsum, A_log, hin);
    scan3_k<<<scan_grid, 64>>>(xb, dl, Bm, Cm, A_log, hin, yb);

    ln_k<<<NTOK, 256>>>(xb, yb, ln_g, ln_b, hy);

    cvt_act<<<NTOK * CH / 1024, 256>>>(hy, ahi, alo);
    mm_bf16<<<mmg, 256, MM_SMEM>>>(ahi, alo, wt + 4*WSZ, wt + 5*WSZ, bq,
                                   nullptr, qh, ql, 4);
    mm_bf16<<<mmg, 256, MM_SMEM>>>(ahi, alo, wt + 6*WSZ, wt + 7*WSZ, bk,
                                   nullptr, kh, kl, 4);
    mm_bf16<<<mmg, 256, MM_SMEM>>>(ahi, alo, wt + 8*WSZ, wt + 9*WSZ, bv,
                                   nullptr, vh, vl, 4);

    flash_mma<<<dim3(SEQ / 64, BATCH * NH), 128, F_SMEM>>>(qh, ql, kh, kl,
                                                           vh, vl, temp, at);

    cvt_act<<<NTOK * CH / 1024, 256>>>(at, ahi, alo);
    mm_bf16<<<mmg, 256, MM_SMEM>>>(ahi, alo, wt + 10*WSZ, wt + 11*WSZ, bo, out,
                                   nullptr, nullptr, 0);
}